// round 8
// baseline (speedup 1.0000x reference)
#include <cuda_runtime.h>
#include <cuda_bf16.h>
#include <math.h>
#include <stdint.h>

#define N_NODES 50000
#define N_EDGES 800000
#define F_DIM   64
#define AVG_D_LOG 2.833f
#define EPS_STD 1e-5f
#define EPS_BN  1e-5f
#define NB 196   // ceil(50000/256); also grid of k_build (co-resident!)
#define A_FLAG 0x40000000u
#define P_FLAG 0x80000000u

typedef unsigned long long ull;

// ---------------- device scratch (all zero-initialized at load) ----------------
__device__ int   g_deg[N_NODES];       // zeroed by k_agg after use
__device__ int   g_off[N_NODES];
__device__ int   g_cursor[N_NODES];
__device__ int   g_esrc[N_EDGES];
__device__ unsigned g_pkt[NB];         // scan lookback state; zeroed by k_agg
__device__ unsigned g_syncA, g_syncB;  // grid barriers; zeroed by k_agg
__device__ float g_agg[(size_t)N_NODES * 256];
__device__ float g_c1[N_NODES];
__device__ float g_c2[N_NODES];
__device__ float g_x[(size_t)N_NODES * F_DIM];
__device__ float g_colsum[F_DIM];
__device__ float g_colsq[F_DIM];
__device__ __nv_bfloat16 g_whi[64 * 768];
__device__ __nv_bfloat16 g_wlo[64 * 768];

// ---------------- helpers -------------------------------------------------------
__device__ __forceinline__ uint32_t smem_u32(const void* p) {
    uint32_t r;
    asm("{ .reg .u64 t; cvta.to.shared.u64 t, %1; cvt.u32.u64 %0, t; }"
        : "=r"(r) : "l"(p));
    return r;
}
__device__ __forceinline__ void ldsm4(uint32_t& r0, uint32_t& r1,
                                      uint32_t& r2, uint32_t& r3, uint32_t a) {
    asm volatile("ldmatrix.sync.aligned.m8n8.x4.shared.b16 {%0,%1,%2,%3}, [%4];"
                 : "=r"(r0), "=r"(r1), "=r"(r2), "=r"(r3) : "r"(a));
}
__device__ __forceinline__ void mma_bf16(float* d,
                                         uint32_t a0, uint32_t a1, uint32_t a2, uint32_t a3,
                                         uint32_t b0, uint32_t b1) {
    asm volatile(
        "mma.sync.aligned.m16n8k16.row.col.f32.bf16.bf16.f32 "
        "{%0,%1,%2,%3}, {%4,%5,%6,%7}, {%8,%9}, {%0,%1,%2,%3};"
        : "+f"(d[0]), "+f"(d[1]), "+f"(d[2]), "+f"(d[3])
        : "r"(a0), "r"(a1), "r"(a2), "r"(a3), "r"(b0), "r"(b1));
}
__device__ __forceinline__ uint32_t packbf(float x, float y) {
    __nv_bfloat162 t;
    t.x = __float2bfloat16_rn(x);
    t.y = __float2bfloat16_rn(y);
    return *(uint32_t*)&t;
}
__device__ __forceinline__ float bferr(float x) {
    return x - __bfloat162float(__float2bfloat16_rn(x));
}
// packed f32x2 (add/fma only — min/max.f32x2 do NOT exist on this toolchain)
__device__ __forceinline__ void add2(ull& d, ull a) {
    asm("add.rn.f32x2 %0, %0, %1;" : "+l"(d) : "l"(a));
}
__device__ __forceinline__ void fma2(ull& d, ull a) {
    asm("fma.rn.f32x2 %0, %1, %1, %0;" : "+l"(d) : "l"(a));
}
__device__ __forceinline__ float lo32(ull v) { return __uint_as_float((unsigned)v); }
__device__ __forceinline__ float hi32(ull v) { return __uint_as_float((unsigned)(v >> 32)); }

// ---------------- K1: fused hist + wprep + scan + scatter ------------------------
// 196 blocks x 256 threads, ALL co-resident (wave 1) -> software grid barriers OK.
__global__ void __launch_bounds__(256) k_build(const int* __restrict__ src,
                                               const int* __restrict__ dst,
                                               const float* __restrict__ W) {
    const int t = threadIdx.x;
    const int bidx = blockIdx.x;
    const int gtid = bidx * 256 + t;
    const int nthreads = NB * 256;          // 50176

    // ---- phase 1: degree histogram (int4) + W split ----
    for (int q = gtid; q < N_EDGES / 4; q += nthreads) {
        int4 d4 = ((const int4*)dst)[q];
        atomicAdd(&g_deg[d4.x], 1);
        atomicAdd(&g_deg[d4.y], 1);
        atomicAdd(&g_deg[d4.z], 1);
        atomicAdd(&g_deg[d4.w], 1);
    }
    for (int i = gtid; i < 768 * 64; i += nthreads) {
        int k = i >> 6;
        int n = i & 63;
        float w = W[i];
        __nv_bfloat16 wh = __float2bfloat16_rn(w);
        __nv_bfloat16 wl = __float2bfloat16_rn(w - __bfloat162float(wh));
        g_whi[n * 768 + k] = wh;
        g_wlo[n * 768 + k] = wl;
    }

    // ---- grid barrier A ----
    __threadfence();
    __syncthreads();
    if (t == 0) {
        atomicAdd(&g_syncA, 1u);
        while (*(volatile unsigned*)&g_syncA < (unsigned)NB) { }
    }
    __syncthreads();
    __threadfence();

    // ---- phase 2: decoupled-lookback scan (block bidx owns node tile bidx) ----
    {
        __shared__ int s[256];
        __shared__ unsigned sprefix;
        int i = bidx * 256 + t;
        int v = (i < N_NODES) ? __ldcg(&g_deg[i]) : 0;
        s[t] = v;
        __syncthreads();
        #pragma unroll
        for (int off = 1; off < 256; off <<= 1) {
            int x = (t >= off) ? s[t - off] : 0;
            __syncthreads();
            s[t] += x;
            __syncthreads();
        }
        int total = s[255];

        if (t == 0) {
            unsigned pub = (bidx == 0) ? (P_FLAG | (unsigned)total)
                                       : (A_FLAG | (unsigned)total);
            atomicExch(&g_pkt[bidx], pub);
            if (bidx == 0) sprefix = 0;
        }

        if (bidx > 0 && t < 32) {
            unsigned running = 0;
            int idx = bidx - 1;
            for (;;) {
                int j = idx - t;
                unsigned p;
                if (j >= 0) {
                    do { p = ((volatile unsigned*)g_pkt)[j]; } while (p == 0);
                } else {
                    p = P_FLAG;
                }
                unsigned pm = __ballot_sync(0xffffffffu, (p & P_FLAG) != 0);
                unsigned val = p & 0x3fffffffu;
                if (pm) {
                    int k = __ffs(pm) - 1;
                    unsigned contrib = (t <= k) ? val : 0;
                    #pragma unroll
                    for (int o = 16; o > 0; o >>= 1)
                        contrib += __shfl_down_sync(0xffffffffu, contrib, o);
                    if (t == 0) sprefix = running + contrib;
                    break;
                } else {
                    unsigned contrib = (j >= 0) ? val : 0;
                    #pragma unroll
                    for (int o = 16; o > 0; o >>= 1)
                        contrib += __shfl_down_sync(0xffffffffu, contrib, o);
                    running += __shfl_sync(0xffffffffu, contrib, 0);
                    idx -= 32;
                }
            }
            if (t == 0)
                atomicExch(&g_pkt[bidx], P_FLAG | (sprefix + (unsigned)total));
        }
        __syncthreads();

        if (i < N_NODES) {
            int ex = (int)sprefix + s[t] - v;
            g_off[i] = ex;
            g_cursor[i] = ex;
        }
    }

    // ---- grid barrier B ----
    __threadfence();
    __syncthreads();
    if (t == 0) {
        atomicAdd(&g_syncB, 1u);
        while (*(volatile unsigned*)&g_syncB < (unsigned)NB) { }
    }
    __syncthreads();
    __threadfence();

    // ---- phase 3: scatter edges (4 per thread iter) ----
    for (int q = gtid; q < N_EDGES / 4; q += nthreads) {
        int4 d4 = ((const int4*)dst)[q];
        int4 s4 = ((const int4*)src)[q];
        int p0 = atomicAdd(&g_cursor[d4.x], 1);
        int p1 = atomicAdd(&g_cursor[d4.y], 1);
        int p2 = atomicAdd(&g_cursor[d4.z], 1);
        int p3 = atomicAdd(&g_cursor[d4.w], 1);
        g_esrc[p0] = s4.x;
        g_esrc[p1] = s4.y;
        g_esrc[p2] = s4.z;
        g_esrc[p3] = s4.w;
    }
}

// ---------------- K2: warp-per-node aggregation ----------------------------------
__global__ void k_agg(const float* __restrict__ h) {
    if (blockIdx.x == 0) {
        int tt = threadIdx.x;
        if (tt < F_DIM) { g_colsum[tt] = 0.f; g_colsq[tt] = 0.f; }
        if (tt < NB) g_pkt[tt] = 0u;
        if (tt == 0) { g_syncA = 0u; g_syncB = 0u; }
    }

    int warp = (blockIdx.x * blockDim.x + threadIdx.x) >> 5;
    int lane = threadIdx.x & 31;
    if (warp >= N_NODES) return;

    int start = g_off[warp];
    int d = g_deg[warp];
    int end = start + d;

    const ull* hl = (const ull*)h + lane;

    ull sum = 0ull;
    ull sq  = 0ull;
    float mx0 = -3.402823466e38f, mx1 = -3.402823466e38f;
    float mn0 =  3.402823466e38f, mn1 =  3.402823466e38f;

    int e = start;
    // scalar prologue to 16B alignment of the index stream
    while (e < end && (e & 3)) {
        ull va = hl[g_esrc[e] * 32];
        add2(sum, va); fma2(sq, va);
        mx0 = fmaxf(mx0, lo32(va)); mx1 = fmaxf(mx1, hi32(va));
        mn0 = fminf(mn0, lo32(va)); mn1 = fminf(mn1, hi32(va));
        e++;
    }
    for (; e + 4 <= end; e += 4) {
        int4 s4 = *(const int4*)(g_esrc + e);
        ull va = hl[s4.x * 32];
        ull vb = hl[s4.y * 32];
        ull vc = hl[s4.z * 32];
        ull vd = hl[s4.w * 32];
        add2(sum, va); fma2(sq, va);
        mx0 = fmaxf(mx0, lo32(va)); mx1 = fmaxf(mx1, hi32(va));
        mn0 = fminf(mn0, lo32(va)); mn1 = fminf(mn1, hi32(va));
        add2(sum, vb); fma2(sq, vb);
        mx0 = fmaxf(mx0, lo32(vb)); mx1 = fmaxf(mx1, hi32(vb));
        mn0 = fminf(mn0, lo32(vb)); mn1 = fminf(mn1, hi32(vb));
        add2(sum, vc); fma2(sq, vc);
        mx0 = fmaxf(mx0, lo32(vc)); mx1 = fmaxf(mx1, hi32(vc));
        mn0 = fminf(mn0, lo32(vc)); mn1 = fminf(mn1, hi32(vc));
        add2(sum, vd); fma2(sq, vd);
        mx0 = fmaxf(mx0, lo32(vd)); mx1 = fmaxf(mx1, hi32(vd));
        mn0 = fminf(mn0, lo32(vd)); mn1 = fminf(mn1, hi32(vd));
    }
    for (; e < end; e++) {
        ull va = hl[g_esrc[e] * 32];
        add2(sum, va); fma2(sq, va);
        mx0 = fmaxf(mx0, lo32(va)); mx1 = fmaxf(mx1, hi32(va));
        mn0 = fminf(mn0, lo32(va)); mn1 = fminf(mn1, hi32(va));
    }

    float* base = g_agg + (size_t)warp * 256;
    if (d > 0) {
        float inv = 1.0f / (float)d;
        float s0 = lo32(sum), s1 = hi32(sum);
        float q0 = lo32(sq),  q1 = hi32(sq);
        float mean0 = s0 * inv, mean1 = s1 * inv;
        float var0 = fmaxf(q0 * inv - mean0 * mean0, 0.f);
        float var1 = fmaxf(q1 * inv - mean1 * mean1, 0.f);
        float std0 = sqrtf(var0 + EPS_STD);
        float std1 = sqrtf(var1 + EPS_STD);
        *(float2*)(base +       2 * lane) = make_float2(mean0, mean1);
        *(float2*)(base +  64 + 2 * lane) = make_float2(mx0, mx1);
        *(float2*)(base + 128 + 2 * lane) = make_float2(mn0, mn1);
        *(float2*)(base + 192 + 2 * lane) = make_float2(std0, std1);
        if (lane == 0) {
            float logD = logf((float)d + 1.0f);
            g_c1[warp] = logD / AVG_D_LOG;
            g_c2[warp] = AVG_D_LOG / fmaxf(logD, 1e-12f);
        }
    } else {
        float2 z = make_float2(0.f, 0.f);
        *(float2*)(base +       2 * lane) = z;
        *(float2*)(base +  64 + 2 * lane) = z;
        *(float2*)(base + 128 + 2 * lane) = z;
        *(float2*)(base + 192 + 2 * lane) = z;
        if (lane == 0) { g_c1[warp] = 0.f; g_c2[warp] = 0.f; }
    }
    if (lane == 0) g_deg[warp] = 0;
}

// ---------------- K3: mma.sync bf16-split GEMM + fused BN column stats ------------
#define AST 144
#define SA_HI 0
#define SA_LO (128 * AST)
#define SB    (2 * 128 * AST)
#define SBUF  (64 * AST)
#define SMEM_MM (SB + 6 * SBUF)

__global__ void __launch_bounds__(256)
k_gemm_mma(const float* __restrict__ bias) {
    extern __shared__ char smem[];
    const uint32_t sb = smem_u32(smem);
    int t = threadIdx.x;
    int w = t >> 5;
    int lane = t & 31;
    int m0 = blockIdx.x * 128;

    float acc[3][8][4];
    #pragma unroll
    for (int p = 0; p < 3; p++)
        #pragma unroll
        for (int nt = 0; nt < 8; nt++)
            #pragma unroll
            for (int j = 0; j < 4; j++) acc[p][nt][j] = 0.f;

    for (int c = 0; c < 4; c++) {
        __syncthreads();
        #pragma unroll
        for (int it = 0; it < 4; it++) {
            int idx = t + it * 256;
            int row = idx >> 3;
            int g = idx & 7;
            int gm = m0 + row;
            uint4 hi = make_uint4(0, 0, 0, 0);
            uint4 lo = make_uint4(0, 0, 0, 0);
            if (gm < N_NODES) {
                const float* srcp = g_agg + (size_t)gm * 256 + c * 64 + g * 8;
                float4 v0 = *(const float4*)srcp;
                float4 v1 = *(const float4*)(srcp + 4);
                hi.x = packbf(v0.x, v0.y); hi.y = packbf(v0.z, v0.w);
                hi.z = packbf(v1.x, v1.y); hi.w = packbf(v1.z, v1.w);
                lo.x = packbf(bferr(v0.x), bferr(v0.y));
                lo.y = packbf(bferr(v0.z), bferr(v0.w));
                lo.z = packbf(bferr(v1.x), bferr(v1.y));
                lo.w = packbf(bferr(v1.z), bferr(v1.w));
            }
            int off = row * AST + g * 16;
            *(uint4*)(smem + SA_HI + off) = hi;
            *(uint4*)(smem + SA_LO + off) = lo;
        }
        #pragma unroll
        for (int it = 0; it < 12; it++) {
            int idx = t + it * 256;
            int buf = idx >> 9;
            int rem = idx & 511;
            int row = rem >> 3;
            int g = rem & 7;
            int p = buf >> 1;
            const __nv_bfloat16* srcp = ((buf & 1) ? g_wlo : g_whi)
                                        + row * 768 + p * 256 + c * 64 + g * 8;
            *(uint4*)(smem + SB + buf * SBUF + row * AST + g * 16) =
                *(const uint4*)srcp;
        }
        __syncthreads();

        #pragma unroll
        for (int ks = 0; ks < 4; ks++) {
            int arow = w * 16 + (lane & 15);
            uint32_t aoff = (uint32_t)(arow * AST + ks * 32 + ((lane >> 4) << 4));
            uint32_t ah0, ah1, ah2, ah3, al0, al1, al2, al3;
            ldsm4(ah0, ah1, ah2, ah3, sb + SA_HI + aoff);
            ldsm4(al0, al1, al2, al3, sb + SA_LO + aoff);

            #pragma unroll
            for (int np = 0; np < 4; np++) {
                int nrow = np * 16 + (lane & 7) + ((lane & 16) ? 8 : 0);
                uint32_t boff = (uint32_t)(nrow * AST + ks * 32 + ((lane & 8) ? 16 : 0));
                #pragma unroll
                for (int p = 0; p < 3; p++) {
                    uint32_t bh0, bh1, bh2, bh3, bl0, bl1, bl2, bl3;
                    ldsm4(bh0, bh1, bh2, bh3, sb + SB + (2 * p)     * SBUF + boff);
                    ldsm4(bl0, bl1, bl2, bl3, sb + SB + (2 * p + 1) * SBUF + boff);
                    float* d0 = acc[p][np * 2];
                    float* d1 = acc[p][np * 2 + 1];
                    mma_bf16(d0, ah0, ah1, ah2, ah3, bh0, bh1);
                    mma_bf16(d0, ah0, ah1, ah2, ah3, bl0, bl1);
                    mma_bf16(d0, al0, al1, al2, al3, bh0, bh1);
                    mma_bf16(d1, ah0, ah1, ah2, ah3, bh2, bh3);
                    mma_bf16(d1, ah0, ah1, ah2, ah3, bl2, bl3);
                    mma_bf16(d1, al0, al1, al2, al3, bh2, bh3);
                }
            }
        }
    }

    __syncthreads();
    float* swsum = (float*)smem;
    float* swsq  = (float*)(smem + 2048);

    int rowA = m0 + w * 16 + (lane >> 2);
    int rowB = rowA + 8;
    bool va = rowA < N_NODES, vb = rowB < N_NODES;
    float c1a = 0.f, c2a = 0.f, c1b = 0.f, c2b = 0.f;
    if (va) { c1a = g_c1[rowA]; c2a = g_c2[rowA]; }
    if (vb) { c1b = g_c1[rowB]; c2b = g_c2[rowB]; }

    #pragma unroll
    for (int nt = 0; nt < 8; nt++) {
        int col = nt * 8 + (lane & 3) * 2;
        float b0 = bias[col];
        float b1 = bias[col + 1];
        float x0a = acc[0][nt][0] + c1a * acc[1][nt][0] + c2a * acc[2][nt][0] + b0;
        float x1a = acc[0][nt][1] + c1a * acc[1][nt][1] + c2a * acc[2][nt][1] + b1;
        float x0b = acc[0][nt][2] + c1b * acc[1][nt][2] + c2b * acc[2][nt][2] + b0;
        float x1b = acc[0][nt][3] + c1b * acc[1][nt][3] + c2b * acc[2][nt][3] + b1;
        if (va) *(float2*)(g_x + (size_t)rowA * 64 + col) = make_float2(x0a, x1a);
        if (vb) *(float2*)(g_x + (size_t)rowB * 64 + col) = make_float2(x0b, x1b);

        float s0 = (va ? x0a : 0.f) + (vb ? x0b : 0.f);
        float s1 = (va ? x1a : 0.f) + (vb ? x1b : 0.f);
        float q0 = (va ? x0a * x0a : 0.f) + (vb ? x0b * x0b : 0.f);
        float q1 = (va ? x1a * x1a : 0.f) + (vb ? x1b * x1b : 0.f);
        #pragma unroll
        for (int o = 4; o <= 16; o <<= 1) {
            s0 += __shfl_xor_sync(0xffffffffu, s0, o);
            s1 += __shfl_xor_sync(0xffffffffu, s1, o);
            q0 += __shfl_xor_sync(0xffffffffu, q0, o);
            q1 += __shfl_xor_sync(0xffffffffu, q1, o);
        }
        if (lane < 4) {
            swsum[w * 64 + nt * 8 + lane * 2]     = s0;
            swsum[w * 64 + nt * 8 + lane * 2 + 1] = s1;
            swsq [w * 64 + nt * 8 + lane * 2]     = q0;
            swsq [w * 64 + nt * 8 + lane * 2 + 1] = q1;
        }
    }
    __syncthreads();
    if (t < 64) {
        float s = 0.f, q = 0.f;
        #pragma unroll
        for (int k = 0; k < 8; k++) {
            s += swsum[k * 64 + t];
            q += swsq[k * 64 + t];
        }
        atomicAdd(&g_colsum[t], s);
        atomicAdd(&g_colsq[t], q);
    }
}

// ---------------- K4: BN + ReLU + residual (float4) -------------------------------
__global__ void k_final(const float* __restrict__ h,
                        const float* __restrict__ gamma,
                        const float* __restrict__ beta,
                        float* __restrict__ out) {
    int i = blockIdx.x * blockDim.x + threadIdx.x;
    if (i >= N_NODES * F_DIM / 4) return;
    int j = (i & 15) * 4;
    const float invN = 1.0f / (float)N_NODES;
    float4 cs = *(const float4*)(g_colsum + j);
    float4 cq = *(const float4*)(g_colsq + j);
    float4 gm = *(const float4*)(gamma + j);
    float4 bt = *(const float4*)(beta + j);
    float4 xv = ((const float4*)g_x)[i];
    float4 hv = ((const float4*)h)[i];
    float4 r;
    {
        float mu = cs.x * invN;
        float inv = rsqrtf(cq.x * invN - mu * mu + EPS_BN);
        r.x = hv.x + fmaxf(gm.x * (xv.x - mu) * inv + bt.x, 0.f);
    }
    {
        float mu = cs.y * invN;
        float inv = rsqrtf(cq.y * invN - mu * mu + EPS_BN);
        r.y = hv.y + fmaxf(gm.y * (xv.y - mu) * inv + bt.y, 0.f);
    }
    {
        float mu = cs.z * invN;
        float inv = rsqrtf(cq.z * invN - mu * mu + EPS_BN);
        r.z = hv.z + fmaxf(gm.z * (xv.z - mu) * inv + bt.z, 0.f);
    }
    {
        float mu = cs.w * invN;
        float inv = rsqrtf(cq.w * invN - mu * mu + EPS_BN);
        r.w = hv.w + fmaxf(gm.w * (xv.w - mu) * inv + bt.w, 0.f);
    }
    ((float4*)out)[i] = r;
}

// ---------------- launch ------------------------------------------------------------
extern "C" void kernel_launch(void* const* d_in, const int* in_sizes, int n_in,
                              void* d_out, int out_size) {
    const float* h     = (const float*)d_in[0];
    const int*   src   = (const int*)d_in[1];
    const int*   dst   = (const int*)d_in[2];
    const float* W     = (const float*)d_in[3];
    const float* b     = (const float*)d_in[4];
    const float* gamma = (const float*)d_in[5];
    const float* beta  = (const float*)d_in[6];
    float* out = (float*)d_out;

    cudaFuncSetAttribute(k_gemm_mma, cudaFuncAttributeMaxDynamicSharedMemorySize, SMEM_MM);

    k_build<<<NB, 256>>>(src, dst, W);
    k_agg<<<(N_NODES + 7) / 8, 256>>>(h);
    k_gemm_mma<<<(N_NODES + 127) / 128, 256, SMEM_MM>>>(b);
    k_final<<<(N_NODES * F_DIM / 4 + 255) / 256, 256>>>(h, gamma, beta, out);
}

// round 9
// speedup vs baseline: 1.0884x; 1.0884x over previous
#include <cuda_runtime.h>
#include <cuda_bf16.h>
#include <math.h>
#include <stdint.h>

#define N_NODES 50000
#define N_EDGES 800000
#define F_DIM   64
#define AVG_D_LOG 2.833f
#define EPS_STD 1e-5f
#define EPS_BN  1e-5f
#define NB 196   // ceil(50000/256)
#define A_FLAG 0x40000000u
#define P_FLAG 0x80000000u

typedef unsigned long long ull;

// ---------------- device scratch (all zero-initialized at load) ----------------
__device__ int   g_deg[N_NODES];       // zeroed by k_agg after use
__device__ int   g_off[N_NODES];
__device__ int   g_cursor[N_NODES];
__device__ int   g_esrc[N_EDGES];
__device__ unsigned g_pkt[NB];         // scan lookback state; zeroed by k_agg
__device__ unsigned g_ahi[(size_t)N_NODES * 128];  // agg rows as bf16x2 words (hi)
__device__ unsigned g_alo[(size_t)N_NODES * 128];  // (lo residual)
__device__ float g_c1[N_NODES];
__device__ float g_c2[N_NODES];
__device__ float g_x[(size_t)N_NODES * F_DIM];
__device__ float g_colsum[F_DIM];
__device__ float g_colsq[F_DIM];
__device__ __nv_bfloat16 g_whi[64 * 768];
__device__ __nv_bfloat16 g_wlo[64 * 768];

// ---------------- helpers -------------------------------------------------------
__device__ __forceinline__ uint32_t smem_u32(const void* p) {
    uint32_t r;
    asm("{ .reg .u64 t; cvta.to.shared.u64 t, %1; cvt.u32.u64 %0, t; }"
        : "=r"(r) : "l"(p));
    return r;
}
__device__ __forceinline__ void ldsm4(uint32_t& r0, uint32_t& r1,
                                      uint32_t& r2, uint32_t& r3, uint32_t a) {
    asm volatile("ldmatrix.sync.aligned.m8n8.x4.shared.b16 {%0,%1,%2,%3}, [%4];"
                 : "=r"(r0), "=r"(r1), "=r"(r2), "=r"(r3) : "r"(a));
}
__device__ __forceinline__ void mma_bf16(float* d,
                                         uint32_t a0, uint32_t a1, uint32_t a2, uint32_t a3,
                                         uint32_t b0, uint32_t b1) {
    asm volatile(
        "mma.sync.aligned.m16n8k16.row.col.f32.bf16.bf16.f32 "
        "{%0,%1,%2,%3}, {%4,%5,%6,%7}, {%8,%9}, {%0,%1,%2,%3};"
        : "+f"(d[0]), "+f"(d[1]), "+f"(d[2]), "+f"(d[3])
        : "r"(a0), "r"(a1), "r"(a2), "r"(a3), "r"(b0), "r"(b1));
}
__device__ __forceinline__ uint32_t packbf(float x, float y) {
    __nv_bfloat162 t;
    t.x = __float2bfloat16_rn(x);
    t.y = __float2bfloat16_rn(y);
    return *(uint32_t*)&t;
}
__device__ __forceinline__ float bferr(float x) {
    return x - __bfloat162float(__float2bfloat16_rn(x));
}
// packed f32x2 (add/fma only — min/max.f32x2 do NOT exist on this toolchain)
__device__ __forceinline__ void add2(ull& d, ull a) {
    asm("add.rn.f32x2 %0, %0, %1;" : "+l"(d) : "l"(a));
}
__device__ __forceinline__ void fma2(ull& d, ull a) {
    asm("fma.rn.f32x2 %0, %1, %1, %0;" : "+l"(d) : "l"(a));
}
__device__ __forceinline__ float lo32(ull v) { return __uint_as_float((unsigned)v); }
__device__ __forceinline__ float hi32(ull v) { return __uint_as_float((unsigned)(v >> 32)); }

// ---------------- K1: degree histogram (int4) + W split ---------------------------
__global__ void k_hist_wprep(const int* __restrict__ dst, const float* __restrict__ W) {
    int t = blockIdx.x * blockDim.x + threadIdx.x;
    if (t < N_EDGES / 4) {
        int4 d4 = ((const int4*)dst)[t];
        atomicAdd(&g_deg[d4.x], 1);
        atomicAdd(&g_deg[d4.y], 1);
        atomicAdd(&g_deg[d4.z], 1);
        atomicAdd(&g_deg[d4.w], 1);
    }
    if (t < 768 * 64) {
        int k = t >> 6;
        int n = t & 63;
        float w = W[t];
        __nv_bfloat16 wh = __float2bfloat16_rn(w);
        __nv_bfloat16 wl = __float2bfloat16_rn(w - __bfloat162float(wh));
        g_whi[n * 768 + k] = wh;
        g_wlo[n * 768 + k] = wl;
    }
}

// ---------------- K2: single-pass decoupled-lookback scan -------------------------
__global__ void k_scan(void) {
    __shared__ int s[256];
    __shared__ unsigned sprefix;
    int t = threadIdx.x;
    int bidx = blockIdx.x;
    int i = bidx * 256 + t;
    int v = (i < N_NODES) ? g_deg[i] : 0;
    s[t] = v;
    __syncthreads();
    #pragma unroll
    for (int off = 1; off < 256; off <<= 1) {
        int x = (t >= off) ? s[t - off] : 0;
        __syncthreads();
        s[t] += x;
        __syncthreads();
    }
    int total = s[255];

    if (t == 0) {
        unsigned pub = (bidx == 0) ? (P_FLAG | (unsigned)total)
                                   : (A_FLAG | (unsigned)total);
        atomicExch(&g_pkt[bidx], pub);
        if (bidx == 0) sprefix = 0;
    }

    if (bidx > 0 && t < 32) {
        unsigned running = 0;
        int idx = bidx - 1;
        for (;;) {
            int j = idx - t;
            unsigned p;
            if (j >= 0) {
                do { p = ((volatile unsigned*)g_pkt)[j]; } while (p == 0);
            } else {
                p = P_FLAG;
            }
            unsigned pm = __ballot_sync(0xffffffffu, (p & P_FLAG) != 0);
            unsigned val = p & 0x3fffffffu;
            if (pm) {
                int k = __ffs(pm) - 1;
                unsigned contrib = (t <= k) ? val : 0;
                #pragma unroll
                for (int o = 16; o > 0; o >>= 1)
                    contrib += __shfl_down_sync(0xffffffffu, contrib, o);
                if (t == 0) sprefix = running + contrib;
                break;
            } else {
                unsigned contrib = (j >= 0) ? val : 0;
                #pragma unroll
                for (int o = 16; o > 0; o >>= 1)
                    contrib += __shfl_down_sync(0xffffffffu, contrib, o);
                running += __shfl_sync(0xffffffffu, contrib, 0);
                idx -= 32;
            }
        }
        if (t == 0)
            atomicExch(&g_pkt[bidx], P_FLAG | (sprefix + (unsigned)total));
    }
    __syncthreads();

    if (i < N_NODES) {
        int ex = (int)sprefix + s[t] - v;
        g_off[i] = ex;
        g_cursor[i] = ex;
    }
}

// ---------------- K3: scatter edges, 4 per thread (MLP=4) -------------------------
__global__ void k_scatter(const int* __restrict__ src, const int* __restrict__ dst) {
    int t = blockIdx.x * blockDim.x + threadIdx.x;
    if (t >= N_EDGES / 4) return;
    int4 d4 = ((const int4*)dst)[t];
    int4 s4 = ((const int4*)src)[t];
    int p0 = atomicAdd(&g_cursor[d4.x], 1);
    int p1 = atomicAdd(&g_cursor[d4.y], 1);
    int p2 = atomicAdd(&g_cursor[d4.z], 1);
    int p3 = atomicAdd(&g_cursor[d4.w], 1);
    g_esrc[p0] = s4.x;
    g_esrc[p1] = s4.y;
    g_esrc[p2] = s4.z;
    g_esrc[p3] = s4.w;
}

// ---------------- K4: warp-per-node aggregation -> bf16 hi/lo output --------------
__global__ void k_agg(const float* __restrict__ h) {
    if (blockIdx.x == 0) {
        int tt = threadIdx.x;
        if (tt < F_DIM) { g_colsum[tt] = 0.f; g_colsq[tt] = 0.f; }
        if (tt < NB) g_pkt[tt] = 0u;
    }

    int warp = (blockIdx.x * blockDim.x + threadIdx.x) >> 5;
    int lane = threadIdx.x & 31;
    if (warp >= N_NODES) return;

    int start = g_off[warp];
    int d = g_deg[warp];
    int end = start + d;

    const ull* hl = (const ull*)h + lane;

    ull sum = 0ull;
    ull sq  = 0ull;
    float mx0 = -3.402823466e38f, mx1 = -3.402823466e38f;
    float mn0 =  3.402823466e38f, mn1 =  3.402823466e38f;

    int e = start;
    while (e < end && (e & 3)) {
        ull va = hl[g_esrc[e] * 32];
        add2(sum, va); fma2(sq, va);
        mx0 = fmaxf(mx0, lo32(va)); mx1 = fmaxf(mx1, hi32(va));
        mn0 = fminf(mn0, lo32(va)); mn1 = fminf(mn1, hi32(va));
        e++;
    }
    for (; e + 4 <= end; e += 4) {
        int4 s4 = *(const int4*)(g_esrc + e);
        ull va = hl[s4.x * 32];
        ull vb = hl[s4.y * 32];
        ull vc = hl[s4.z * 32];
        ull vd = hl[s4.w * 32];
        add2(sum, va); fma2(sq, va);
        mx0 = fmaxf(mx0, lo32(va)); mx1 = fmaxf(mx1, hi32(va));
        mn0 = fminf(mn0, lo32(va)); mn1 = fminf(mn1, hi32(va));
        add2(sum, vb); fma2(sq, vb);
        mx0 = fmaxf(mx0, lo32(vb)); mx1 = fmaxf(mx1, hi32(vb));
        mn0 = fminf(mn0, lo32(vb)); mn1 = fminf(mn1, hi32(vb));
        add2(sum, vc); fma2(sq, vc);
        mx0 = fmaxf(mx0, lo32(vc)); mx1 = fmaxf(mx1, hi32(vc));
        mn0 = fminf(mn0, lo32(vc)); mn1 = fminf(mn1, hi32(vc));
        add2(sum, vd); fma2(sq, vd);
        mx0 = fmaxf(mx0, lo32(vd)); mx1 = fmaxf(mx1, hi32(vd));
        mn0 = fminf(mn0, lo32(vd)); mn1 = fminf(mn1, hi32(vd));
    }
    for (; e < end; e++) {
        ull va = hl[g_esrc[e] * 32];
        add2(sum, va); fma2(sq, va);
        mx0 = fmaxf(mx0, lo32(va)); mx1 = fmaxf(mx1, hi32(va));
        mn0 = fminf(mn0, lo32(va)); mn1 = fminf(mn1, hi32(va));
    }

    unsigned* ah = g_ahi + (size_t)warp * 128 + lane;
    unsigned* al = g_alo + (size_t)warp * 128 + lane;
    if (d > 0) {
        float inv = 1.0f / (float)d;
        float s0 = lo32(sum), s1 = hi32(sum);
        float q0 = lo32(sq),  q1 = hi32(sq);
        float mean0 = s0 * inv, mean1 = s1 * inv;
        float var0 = fmaxf(q0 * inv - mean0 * mean0, 0.f);
        float var1 = fmaxf(q1 * inv - mean1 * mean1, 0.f);
        float std0 = sqrtf(var0 + EPS_STD);
        float std1 = sqrtf(var1 + EPS_STD);
        // sections: 0=mean 1=max 2=min 3=std; each section = 32 bf16x2 words
        ah[0]  = packbf(mean0, mean1);
        ah[32] = packbf(mx0, mx1);
        ah[64] = packbf(mn0, mn1);
        ah[96] = packbf(std0, std1);
        al[0]  = packbf(bferr(mean0), bferr(mean1));
        al[32] = packbf(bferr(mx0), bferr(mx1));
        al[64] = packbf(bferr(mn0), bferr(mn1));
        al[96] = packbf(bferr(std0), bferr(std1));
        if (lane == 0) {
            float logD = logf((float)d + 1.0f);
            g_c1[warp] = logD / AVG_D_LOG;
            g_c2[warp] = AVG_D_LOG / fmaxf(logD, 1e-12f);
        }
    } else {
        ah[0] = 0u; ah[32] = 0u; ah[64] = 0u; ah[96] = 0u;
        al[0] = 0u; al[32] = 0u; al[64] = 0u; al[96] = 0u;
        if (lane == 0) { g_c1[warp] = 0.f; g_c2[warp] = 0.f; }
    }
    if (lane == 0) g_deg[warp] = 0;
}

// ---------------- K5: mma.sync bf16-split GEMM + fused BN column stats ------------
#define AST 144
#define SA_HI 0
#define SA_LO (128 * AST)
#define SB    (2 * 128 * AST)
#define SBUF  (64 * AST)
#define SMEM_MM (SB + 6 * SBUF)

__global__ void __launch_bounds__(256)
k_gemm_mma(const float* __restrict__ bias) {
    extern __shared__ char smem[];
    const uint32_t sb = smem_u32(smem);
    int t = threadIdx.x;
    int w = t >> 5;
    int lane = t & 31;
    int m0 = blockIdx.x * 128;

    float acc[3][8][4];
    #pragma unroll
    for (int p = 0; p < 3; p++)
        #pragma unroll
        for (int nt = 0; nt < 8; nt++)
            #pragma unroll
            for (int j = 0; j < 4; j++) acc[p][nt][j] = 0.f;

    for (int c = 0; c < 4; c++) {
        __syncthreads();
        // ---- A chunk: direct bf16 hi/lo copy (section c of each row) ----
        #pragma unroll
        for (int it = 0; it < 4; it++) {
            int idx = t + it * 256;       // 0..1023
            int row = idx >> 3;
            int g = idx & 7;
            int gm = m0 + row;
            uint4 hi = make_uint4(0, 0, 0, 0);
            uint4 lo = make_uint4(0, 0, 0, 0);
            if (gm < N_NODES) {
                size_t base = (size_t)gm * 128 + c * 32 + g * 4;
                hi = *(const uint4*)(g_ahi + base);
                lo = *(const uint4*)(g_alo + base);
            }
            int off = row * AST + g * 16;
            *(uint4*)(smem + SA_HI + off) = hi;
            *(uint4*)(smem + SA_LO + off) = lo;
        }
        // ---- B chunk ----
        #pragma unroll
        for (int it = 0; it < 12; it++) {
            int idx = t + it * 256;
            int buf = idx >> 9;
            int rem = idx & 511;
            int row = rem >> 3;
            int g = rem & 7;
            int p = buf >> 1;
            const __nv_bfloat16* srcp = ((buf & 1) ? g_wlo : g_whi)
                                        + row * 768 + p * 256 + c * 64 + g * 8;
            *(uint4*)(smem + SB + buf * SBUF + row * AST + g * 16) =
                *(const uint4*)srcp;
        }
        __syncthreads();

        #pragma unroll
        for (int ks = 0; ks < 4; ks++) {
            int arow = w * 16 + (lane & 15);
            uint32_t aoff = (uint32_t)(arow * AST + ks * 32 + ((lane >> 4) << 4));
            uint32_t ah0, ah1, ah2, ah3, al0, al1, al2, al3;
            ldsm4(ah0, ah1, ah2, ah3, sb + SA_HI + aoff);
            ldsm4(al0, al1, al2, al3, sb + SA_LO + aoff);

            #pragma unroll
            for (int np = 0; np < 4; np++) {
                int nrow = np * 16 + (lane & 7) + ((lane & 16) ? 8 : 0);
                uint32_t boff = (uint32_t)(nrow * AST + ks * 32 + ((lane & 8) ? 16 : 0));
                #pragma unroll
                for (int p = 0; p < 3; p++) {
                    uint32_t bh0, bh1, bh2, bh3, bl0, bl1, bl2, bl3;
                    ldsm4(bh0, bh1, bh2, bh3, sb + SB + (2 * p)     * SBUF + boff);
                    ldsm4(bl0, bl1, bl2, bl3, sb + SB + (2 * p + 1) * SBUF + boff);
                    float* d0 = acc[p][np * 2];
                    float* d1 = acc[p][np * 2 + 1];
                    mma_bf16(d0, ah0, ah1, ah2, ah3, bh0, bh1);
                    mma_bf16(d0, ah0, ah1, ah2, ah3, bl0, bl1);
                    mma_bf16(d0, al0, al1, al2, al3, bh0, bh1);
                    mma_bf16(d1, ah0, ah1, ah2, ah3, bh2, bh3);
                    mma_bf16(d1, ah0, ah1, ah2, ah3, bl2, bl3);
                    mma_bf16(d1, al0, al1, al2, al3, bh2, bh3);
                }
            }
        }
    }

    __syncthreads();
    float* swsum = (float*)smem;
    float* swsq  = (float*)(smem + 2048);

    int rowA = m0 + w * 16 + (lane >> 2);
    int rowB = rowA + 8;
    bool va = rowA < N_NODES, vb = rowB < N_NODES;
    float c1a = 0.f, c2a = 0.f, c1b = 0.f, c2b = 0.f;
    if (va) { c1a = g_c1[rowA]; c2a = g_c2[rowA]; }
    if (vb) { c1b = g_c1[rowB]; c2b = g_c2[rowB]; }

    #pragma unroll
    for (int nt = 0; nt < 8; nt++) {
        int col = nt * 8 + (lane & 3) * 2;
        float b0 = bias[col];
        float b1 = bias[col + 1];
        float x0a = acc[0][nt][0] + c1a * acc[1][nt][0] + c2a * acc[2][nt][0] + b0;
        float x1a = acc[0][nt][1] + c1a * acc[1][nt][1] + c2a * acc[2][nt][1] + b1;
        float x0b = acc[0][nt][2] + c1b * acc[1][nt][2] + c2b * acc[2][nt][2] + b0;
        float x1b = acc[0][nt][3] + c1b * acc[1][nt][3] + c2b * acc[2][nt][3] + b1;
        if (va) *(float2*)(g_x + (size_t)rowA * 64 + col) = make_float2(x0a, x1a);
        if (vb) *(float2*)(g_x + (size_t)rowB * 64 + col) = make_float2(x0b, x1b);

        float s0 = (va ? x0a : 0.f) + (vb ? x0b : 0.f);
        float s1 = (va ? x1a : 0.f) + (vb ? x1b : 0.f);
        float q0 = (va ? x0a * x0a : 0.f) + (vb ? x0b * x0b : 0.f);
        float q1 = (va ? x1a * x1a : 0.f) + (vb ? x1b * x1b : 0.f);
        #pragma unroll
        for (int o = 4; o <= 16; o <<= 1) {
            s0 += __shfl_xor_sync(0xffffffffu, s0, o);
            s1 += __shfl_xor_sync(0xffffffffu, s1, o);
            q0 += __shfl_xor_sync(0xffffffffu, q0, o);
            q1 += __shfl_xor_sync(0xffffffffu, q1, o);
        }
        if (lane < 4) {
            swsum[w * 64 + nt * 8 + lane * 2]     = s0;
            swsum[w * 64 + nt * 8 + lane * 2 + 1] = s1;
            swsq [w * 64 + nt * 8 + lane * 2]     = q0;
            swsq [w * 64 + nt * 8 + lane * 2 + 1] = q1;
        }
    }
    __syncthreads();
    if (t < 64) {
        float s = 0.f, q = 0.f;
        #pragma unroll
        for (int k = 0; k < 8; k++) {
            s += swsum[k * 64 + t];
            q += swsq[k * 64 + t];
        }
        atomicAdd(&g_colsum[t], s);
        atomicAdd(&g_colsq[t], q);
    }
}

// ---------------- K6: BN + ReLU + residual (float4) -------------------------------
__global__ void k_final(const float* __restrict__ h,
                        const float* __restrict__ gamma,
                        const float* __restrict__ beta,
                        float* __restrict__ out) {
    int i = blockIdx.x * blockDim.x + threadIdx.x;
    if (i >= N_NODES * F_DIM / 4) return;
    int j = (i & 15) * 4;
    const float invN = 1.0f / (float)N_NODES;
    float4 cs = *(const float4*)(g_colsum + j);
    float4 cq = *(const float4*)(g_colsq + j);
    float4 gm = *(const float4*)(gamma + j);
    float4 bt = *(const float4*)(beta + j);
    float4 xv = ((const float4*)g_x)[i];
    float4 hv = ((const float4*)h)[i];
    float4 r;
    {
        float mu = cs.x * invN;
        float inv = rsqrtf(cq.x * invN - mu * mu + EPS_BN);
        r.x = hv.x + fmaxf(gm.x * (xv.x - mu) * inv + bt.x, 0.f);
    }
    {
        float mu = cs.y * invN;
        float inv = rsqrtf(cq.y * invN - mu * mu + EPS_BN);
        r.y = hv.y + fmaxf(gm.y * (xv.y - mu) * inv + bt.y, 0.f);
    }
    {
        float mu = cs.z * invN;
        float inv = rsqrtf(cq.z * invN - mu * mu + EPS_BN);
        r.z = hv.z + fmaxf(gm.z * (xv.z - mu) * inv + bt.z, 0.f);
    }
    {
        float mu = cs.w * invN;
        float inv = rsqrtf(cq.w * invN - mu * mu + EPS_BN);
        r.w = hv.w + fmaxf(gm.w * (xv.w - mu) * inv + bt.w, 0.f);
    }
    ((float4*)out)[i] = r;
}

// ---------------- launch ------------------------------------------------------------
extern "C" void kernel_launch(void* const* d_in, const int* in_sizes, int n_in,
                              void* d_out, int out_size) {
    const float* h     = (const float*)d_in[0];
    const int*   src   = (const int*)d_in[1];
    const int*   dst   = (const int*)d_in[2];
    const float* W     = (const float*)d_in[3];
    const float* b     = (const float*)d_in[4];
    const float* gamma = (const float*)d_in[5];
    const float* beta  = (const float*)d_in[6];
    float* out = (float*)d_out;

    cudaFuncSetAttribute(k_gemm_mma, cudaFuncAttributeMaxDynamicSharedMemorySize, SMEM_MM);

    k_hist_wprep<<<(N_EDGES / 4 + 255) / 256, 256>>>(dst, W);
    k_scan<<<NB, 256>>>();
    k_scatter<<<(N_EDGES / 4 + 255) / 256, 256>>>(src, dst);
    k_agg<<<(N_NODES + 7) / 8, 256>>>(h);
    k_gemm_mma<<<(N_NODES + 127) / 128, 256, SMEM_MM>>>(b);
    k_final<<<(N_NODES * F_DIM / 4 + 255) / 256, 256>>>(h, gamma, beta, out);
}

// round 10
// speedup vs baseline: 1.1535x; 1.0598x over previous
#include <cuda_runtime.h>
#include <cuda_fp16.h>
#include <math.h>
#include <stdint.h>

#define N_NODES 50000
#define N_EDGES 800000
#define F_DIM   64
#define AVG_D_LOG 2.833f
#define EPS_STD 1e-5f
#define EPS_BN  1e-5f
#define NB 196   // ceil(50000/256)
#define A_FLAG 0x40000000u
#define P_FLAG 0x80000000u

typedef unsigned long long ull;

// ---------------- device scratch (all zero-initialized at load) ----------------
__device__ int   g_deg[N_NODES];       // zeroed by k_agg after use
__device__ int   g_off[N_NODES];
__device__ int   g_cursor[N_NODES];
__device__ int   g_esrc[N_EDGES];
__device__ unsigned g_pkt[NB];         // scan lookback state; zeroed by k_agg
__device__ unsigned g_a16[(size_t)N_NODES * 128];  // agg rows as fp16x2 words
__device__ float g_c1[N_NODES];
__device__ float g_c2[N_NODES];
__device__ float g_x[(size_t)N_NODES * F_DIM];
__device__ float g_colsum[F_DIM];
__device__ float g_colsq[F_DIM];
__device__ __half g_whi[64 * 768];     // W^T hi split [n][k]
__device__ __half g_wlo[64 * 768];     // W^T lo residual

// ---------------- helpers -------------------------------------------------------
__device__ __forceinline__ uint32_t smem_u32(const void* p) {
    uint32_t r;
    asm("{ .reg .u64 t; cvta.to.shared.u64 t, %1; cvt.u32.u64 %0, t; }"
        : "=r"(r) : "l"(p));
    return r;
}
__device__ __forceinline__ void ldsm4(uint32_t& r0, uint32_t& r1,
                                      uint32_t& r2, uint32_t& r3, uint32_t a) {
    asm volatile("ldmatrix.sync.aligned.m8n8.x4.shared.b16 {%0,%1,%2,%3}, [%4];"
                 : "=r"(r0), "=r"(r1), "=r"(r2), "=r"(r3) : "r"(a));
}
__device__ __forceinline__ void mma_f16(float* d,
                                        uint32_t a0, uint32_t a1, uint32_t a2, uint32_t a3,
                                        uint32_t b0, uint32_t b1) {
    asm volatile(
        "mma.sync.aligned.m16n8k16.row.col.f32.f16.f16.f32 "
        "{%0,%1,%2,%3}, {%4,%5,%6,%7}, {%8,%9}, {%0,%1,%2,%3};"
        : "+f"(d[0]), "+f"(d[1]), "+f"(d[2]), "+f"(d[3])
        : "r"(a0), "r"(a1), "r"(a2), "r"(a3), "r"(b0), "r"(b1));
}
__device__ __forceinline__ uint32_t packh(float x, float y) {
    __half2 t;
    t.x = __float2half_rn(x);
    t.y = __float2half_rn(y);
    return *(uint32_t*)&t;
}
// packed f32x2 (add/fma only on this toolchain)
__device__ __forceinline__ void add2(ull& d, ull a) {
    asm("add.rn.f32x2 %0, %0, %1;" : "+l"(d) : "l"(a));
}
__device__ __forceinline__ void fma2(ull& d, ull a) {
    asm("fma.rn.f32x2 %0, %1, %1, %0;" : "+l"(d) : "l"(a));
}
__device__ __forceinline__ float lo32(ull v) { return __uint_as_float((unsigned)v); }
__device__ __forceinline__ float hi32(ull v) { return __uint_as_float((unsigned)(v >> 32)); }

// ---------------- K1: degree histogram (int4) + W fp16 split ---------------------
__global__ void k_hist_wprep(const int* __restrict__ dst, const float* __restrict__ W) {
    int t = blockIdx.x * blockDim.x + threadIdx.x;
    if (t < N_EDGES / 4) {
        int4 d4 = ((const int4*)dst)[t];
        atomicAdd(&g_deg[d4.x], 1);
        atomicAdd(&g_deg[d4.y], 1);
        atomicAdd(&g_deg[d4.z], 1);
        atomicAdd(&g_deg[d4.w], 1);
    }
    if (t < 768 * 64) {
        int k = t >> 6;
        int n = t & 63;
        float w = W[t];
        __half wh = __float2half_rn(w);
        __half wl = __float2half_rn(w - __half2float(wh));
        g_whi[n * 768 + k] = wh;
        g_wlo[n * 768 + k] = wl;
    }
}

// ---------------- K2: single-pass decoupled-lookback scan -------------------------
__global__ void k_scan(void) {
    __shared__ int s[256];
    __shared__ unsigned sprefix;
    int t = threadIdx.x;
    int bidx = blockIdx.x;
    int i = bidx * 256 + t;
    int v = (i < N_NODES) ? g_deg[i] : 0;
    s[t] = v;
    __syncthreads();
    #pragma unroll
    for (int off = 1; off < 256; off <<= 1) {
        int x = (t >= off) ? s[t - off] : 0;
        __syncthreads();
        s[t] += x;
        __syncthreads();
    }
    int total = s[255];

    if (t == 0) {
        unsigned pub = (bidx == 0) ? (P_FLAG | (unsigned)total)
                                   : (A_FLAG | (unsigned)total);
        atomicExch(&g_pkt[bidx], pub);
        if (bidx == 0) sprefix = 0;
    }

    if (bidx > 0 && t < 32) {
        unsigned running = 0;
        int idx = bidx - 1;
        for (;;) {
            int j = idx - t;
            unsigned p;
            if (j >= 0) {
                do { p = ((volatile unsigned*)g_pkt)[j]; } while (p == 0);
            } else {
                p = P_FLAG;
            }
            unsigned pm = __ballot_sync(0xffffffffu, (p & P_FLAG) != 0);
            unsigned val = p & 0x3fffffffu;
            if (pm) {
                int k = __ffs(pm) - 1;
                unsigned contrib = (t <= k) ? val : 0;
                #pragma unroll
                for (int o = 16; o > 0; o >>= 1)
                    contrib += __shfl_down_sync(0xffffffffu, contrib, o);
                if (t == 0) sprefix = running + contrib;
                break;
            } else {
                unsigned contrib = (j >= 0) ? val : 0;
                #pragma unroll
                for (int o = 16; o > 0; o >>= 1)
                    contrib += __shfl_down_sync(0xffffffffu, contrib, o);
                running += __shfl_sync(0xffffffffu, contrib, 0);
                idx -= 32;
            }
        }
        if (t == 0)
            atomicExch(&g_pkt[bidx], P_FLAG | (sprefix + (unsigned)total));
    }
    __syncthreads();

    if (i < N_NODES) {
        int ex = (int)sprefix + s[t] - v;
        g_off[i] = ex;
        g_cursor[i] = ex;
    }
}

// ---------------- K3: scatter edges, 4 per thread (MLP=4) -------------------------
__global__ void k_scatter(const int* __restrict__ src, const int* __restrict__ dst) {
    int t = blockIdx.x * blockDim.x + threadIdx.x;
    if (t >= N_EDGES / 4) return;
    int4 d4 = ((const int4*)dst)[t];
    int4 s4 = ((const int4*)src)[t];
    int p0 = atomicAdd(&g_cursor[d4.x], 1);
    int p1 = atomicAdd(&g_cursor[d4.y], 1);
    int p2 = atomicAdd(&g_cursor[d4.z], 1);
    int p3 = atomicAdd(&g_cursor[d4.w], 1);
    g_esrc[p0] = s4.x;
    g_esrc[p1] = s4.y;
    g_esrc[p2] = s4.z;
    g_esrc[p3] = s4.w;
}

// ---------------- K4: warp-per-node aggregation, dual accumulator banks -----------
__global__ void k_agg(const float* __restrict__ h) {
    if (blockIdx.x == 0) {
        int tt = threadIdx.x;
        if (tt < F_DIM) { g_colsum[tt] = 0.f; g_colsq[tt] = 0.f; }
        if (tt < NB) g_pkt[tt] = 0u;
    }

    int warp = (blockIdx.x * blockDim.x + threadIdx.x) >> 5;
    int lane = threadIdx.x & 31;
    if (warp >= N_NODES) return;

    int start = g_off[warp];
    int d = g_deg[warp];
    int end = start + d;

    const ull* hl = (const ull*)h + lane;

    // dual accumulator banks: halve the fixed-lat RAW chains
    ull sumA = 0ull, sumB = 0ull;
    ull sqA  = 0ull, sqB  = 0ull;
    float mxA0 = -3.402823466e38f, mxA1 = -3.402823466e38f;
    float mxB0 = -3.402823466e38f, mxB1 = -3.402823466e38f;
    float mnA0 =  3.402823466e38f, mnA1 =  3.402823466e38f;
    float mnB0 =  3.402823466e38f, mnB1 =  3.402823466e38f;

    int e = start;
    while (e < end && (e & 3)) {
        ull va = hl[g_esrc[e] * 32];
        add2(sumA, va); fma2(sqA, va);
        mxA0 = fmaxf(mxA0, lo32(va)); mxA1 = fmaxf(mxA1, hi32(va));
        mnA0 = fminf(mnA0, lo32(va)); mnA1 = fminf(mnA1, hi32(va));
        e++;
    }
    for (; e + 4 <= end; e += 4) {
        int4 s4 = *(const int4*)(g_esrc + e);
        ull va = hl[s4.x * 32];
        ull vb = hl[s4.y * 32];
        ull vc = hl[s4.z * 32];
        ull vd = hl[s4.w * 32];
        add2(sumA, va); fma2(sqA, va);
        mxA0 = fmaxf(mxA0, lo32(va)); mxA1 = fmaxf(mxA1, hi32(va));
        mnA0 = fminf(mnA0, lo32(va)); mnA1 = fminf(mnA1, hi32(va));
        add2(sumB, vb); fma2(sqB, vb);
        mxB0 = fmaxf(mxB0, lo32(vb)); mxB1 = fmaxf(mxB1, hi32(vb));
        mnB0 = fminf(mnB0, lo32(vb)); mnB1 = fminf(mnB1, hi32(vb));
        add2(sumA, vc); fma2(sqA, vc);
        mxA0 = fmaxf(mxA0, lo32(vc)); mxA1 = fmaxf(mxA1, hi32(vc));
        mnA0 = fminf(mnA0, lo32(vc)); mnA1 = fminf(mnA1, hi32(vc));
        add2(sumB, vd); fma2(sqB, vd);
        mxB0 = fmaxf(mxB0, lo32(vd)); mxB1 = fmaxf(mxB1, hi32(vd));
        mnB0 = fminf(mnB0, lo32(vd)); mnB1 = fminf(mnB1, hi32(vd));
    }
    for (; e < end; e++) {
        ull va = hl[g_esrc[e] * 32];
        add2(sumA, va); fma2(sqA, va);
        mxA0 = fmaxf(mxA0, lo32(va)); mxA1 = fmaxf(mxA1, hi32(va));
        mnA0 = fminf(mnA0, lo32(va)); mnA1 = fminf(mnA1, hi32(va));
    }
    // merge banks
    add2(sumA, sumB);
    add2(sqA, sqB);
    float mx0 = fmaxf(mxA0, mxB0), mx1 = fmaxf(mxA1, mxB1);
    float mn0 = fminf(mnA0, mnB0), mn1 = fminf(mnA1, mnB1);

    unsigned* ar = g_a16 + (size_t)warp * 128 + lane;
    if (d > 0) {
        float inv = 1.0f / (float)d;
        float s0 = lo32(sumA), s1 = hi32(sumA);
        float q0 = lo32(sqA),  q1 = hi32(sqA);
        float mean0 = s0 * inv, mean1 = s1 * inv;
        float var0 = fmaxf(q0 * inv - mean0 * mean0, 0.f);
        float var1 = fmaxf(q1 * inv - mean1 * mean1, 0.f);
        float std0 = sqrtf(var0 + EPS_STD);
        float std1 = sqrtf(var1 + EPS_STD);
        // sections: 0=mean 1=max 2=min 3=std; 32 fp16x2 words each
        ar[0]  = packh(mean0, mean1);
        ar[32] = packh(mx0, mx1);
        ar[64] = packh(mn0, mn1);
        ar[96] = packh(std0, std1);
        if (lane == 0) {
            float logD = logf((float)d + 1.0f);
            g_c1[warp] = logD / AVG_D_LOG;
            g_c2[warp] = AVG_D_LOG / fmaxf(logD, 1e-12f);
        }
    } else {
        ar[0] = 0u; ar[32] = 0u; ar[64] = 0u; ar[96] = 0u;
        if (lane == 0) { g_c1[warp] = 0.f; g_c2[warp] = 0.f; }
    }
    if (lane == 0) g_deg[warp] = 0;
}

// ---------------- K5: mma.sync fp16 GEMM (A single fp16, W hi/lo) -----------------
// D_p = A @ (Wph + Wpl), fp32 accum; 2 MMA terms instead of 3.
#define AST 144
#define SA    0
#define SB    (128 * AST)             // 18432
#define SBUF  (64 * AST)              // 9216
#define SMEM_MM (SB + 6 * SBUF)       // 73728

__global__ void __launch_bounds__(256)
k_gemm_mma(const float* __restrict__ bias) {
    extern __shared__ char smem[];
    const uint32_t sb = smem_u32(smem);
    int t = threadIdx.x;
    int w = t >> 5;
    int lane = t & 31;
    int m0 = blockIdx.x * 128;

    float acc[3][8][4];
    #pragma unroll
    for (int p = 0; p < 3; p++)
        #pragma unroll
        for (int nt = 0; nt < 8; nt++)
            #pragma unroll
            for (int j = 0; j < 4; j++) acc[p][nt][j] = 0.f;

    for (int c = 0; c < 4; c++) {
        __syncthreads();
        // ---- A chunk: direct fp16 copy (section c of each node row) ----
        #pragma unroll
        for (int it = 0; it < 4; it++) {
            int idx = t + it * 256;       // 0..1023
            int row = idx >> 3;
            int g = idx & 7;
            int gm = m0 + row;
            uint4 v = make_uint4(0, 0, 0, 0);
            if (gm < N_NODES)
                v = *(const uint4*)(g_a16 + (size_t)gm * 128 + c * 32 + g * 4);
            *(uint4*)(smem + SA + row * AST + g * 16) = v;
        }
        // ---- B chunk: 6 bufs (p0h,p0l,p1h,p1l,p2h,p2l), 64 n-rows x 64 k ----
        #pragma unroll
        for (int it = 0; it < 12; it++) {
            int idx = t + it * 256;
            int buf = idx >> 9;
            int rem = idx & 511;
            int row = rem >> 3;
            int g = rem & 7;
            int p = buf >> 1;
            const __half* srcp = ((buf & 1) ? g_wlo : g_whi)
                                 + row * 768 + p * 256 + c * 64 + g * 8;
            *(uint4*)(smem + SB + buf * SBUF + row * AST + g * 16) =
                *(const uint4*)srcp;
        }
        __syncthreads();

        #pragma unroll
        for (int ks = 0; ks < 4; ks++) {
            int arow = w * 16 + (lane & 15);
            uint32_t aoff = (uint32_t)(arow * AST + ks * 32 + ((lane >> 4) << 4));
            uint32_t a0, a1, a2, a3;
            ldsm4(a0, a1, a2, a3, sb + SA + aoff);

            #pragma unroll
            for (int np = 0; np < 4; np++) {
                int nrow = np * 16 + (lane & 7) + ((lane & 16) ? 8 : 0);
                uint32_t boff = (uint32_t)(nrow * AST + ks * 32 + ((lane & 8) ? 16 : 0));
                #pragma unroll
                for (int p = 0; p < 3; p++) {
                    uint32_t bh0, bh1, bh2, bh3, bl0, bl1, bl2, bl3;
                    ldsm4(bh0, bh1, bh2, bh3, sb + SB + (2 * p)     * SBUF + boff);
                    ldsm4(bl0, bl1, bl2, bl3, sb + SB + (2 * p + 1) * SBUF + boff);
                    float* d0 = acc[p][np * 2];
                    float* d1 = acc[p][np * 2 + 1];
                    mma_f16(d0, a0, a1, a2, a3, bh0, bh1);
                    mma_f16(d0, a0, a1, a2, a3, bl0, bl1);
                    mma_f16(d1, a0, a1, a2, a3, bh2, bh3);
                    mma_f16(d1, a0, a1, a2, a3, bl2, bl3);
                }
            }
        }
    }

    __syncthreads();
    float* swsum = (float*)smem;
    float* swsq  = (float*)(smem + 2048);

    int rowA = m0 + w * 16 + (lane >> 2);
    int rowB = rowA + 8;
    bool va = rowA < N_NODES, vb = rowB < N_NODES;
    float c1a = 0.f, c2a = 0.f, c1b = 0.f, c2b = 0.f;
    if (va) { c1a = g_c1[rowA]; c2a = g_c2[rowA]; }
    if (vb) { c1b = g_c1[rowB]; c2b = g_c2[rowB]; }

    #pragma unroll
    for (int nt = 0; nt < 8; nt++) {
        int col = nt * 8 + (lane & 3) * 2;
        float b0 = bias[col];
        float b1 = bias[col + 1];
        float x0a = acc[0][nt][0] + c1a * acc[1][nt][0] + c2a * acc[2][nt][0] + b0;
        float x1a = acc[0][nt][1] + c1a * acc[1][nt][1] + c2a * acc[2][nt][1] + b1;
        float x0b = acc[0][nt][2] + c1b * acc[1][nt][2] + c2b * acc[2][nt][2] + b0;
        float x1b = acc[0][nt][3] + c1b * acc[1][nt][3] + c2b * acc[2][nt][3] + b1;
        if (va) *(float2*)(g_x + (size_t)rowA * 64 + col) = make_float2(x0a, x1a);
        if (vb) *(float2*)(g_x + (size_t)rowB * 64 + col) = make_float2(x0b, x1b);

        float s0 = (va ? x0a : 0.f) + (vb ? x0b : 0.f);
        float s1 = (va ? x1a : 0.f) + (vb ? x1b : 0.f);
        float q0 = (va ? x0a * x0a : 0.f) + (vb ? x0b * x0b : 0.f);
        float q1 = (va ? x1a * x1a : 0.f) + (vb ? x1b * x1b : 0.f);
        #pragma unroll
        for (int o = 4; o <= 16; o <<= 1) {
            s0 += __shfl_xor_sync(0xffffffffu, s0, o);
            s1 += __shfl_xor_sync(0xffffffffu, s1, o);
            q0 += __shfl_xor_sync(0xffffffffu, q0, o);
            q1 += __shfl_xor_sync(0xffffffffu, q1, o);
        }
        if (lane < 4) {
            swsum[w * 64 + nt * 8 + lane * 2]     = s0;
            swsum[w * 64 + nt * 8 + lane * 2 + 1] = s1;
            swsq [w * 64 + nt * 8 + lane * 2]     = q0;
            swsq [w * 64 + nt * 8 + lane * 2 + 1] = q1;
        }
    }
    __syncthreads();
    if (t < 64) {
        float s = 0.f, q = 0.f;
        #pragma unroll
        for (int k = 0; k < 8; k++) {
            s += swsum[k * 64 + t];
            q += swsq[k * 64 + t];
        }
        atomicAdd(&g_colsum[t], s);
        atomicAdd(&g_colsq[t], q);
    }
}

// ---------------- K6: BN + ReLU + residual (float4) -------------------------------
__global__ void k_final(const float* __restrict__ h,
                        const float* __restrict__ gamma,
                        const float* __restrict__ beta,
                        float* __restrict__ out) {
    int i = blockIdx.x * blockDim.x + threadIdx.x;
    if (i >= N_NODES * F_DIM / 4) return;
    int j = (i & 15) * 4;
    const float invN = 1.0f / (float)N_NODES;
    float4 cs = *(const float4*)(g_colsum + j);
    float4 cq = *(const float4*)(g_colsq + j);
    float4 gm = *(const float4*)(gamma + j);
    float4 bt = *(const float4*)(beta + j);
    float4 xv = ((const float4*)g_x)[i];
    float4 hv = ((const float4*)h)[i];
    float4 r;
    {
        float mu = cs.x * invN;
        float inv = rsqrtf(cq.x * invN - mu * mu + EPS_BN);
        r.x = hv.x + fmaxf(gm.x * (xv.x - mu) * inv + bt.x, 0.f);
    }
    {
        float mu = cs.y * invN;
        float inv = rsqrtf(cq.y * invN - mu * mu + EPS_BN);
        r.y = hv.y + fmaxf(gm.y * (xv.y - mu) * inv + bt.y, 0.f);
    }
    {
        float mu = cs.z * invN;
        float inv = rsqrtf(cq.z * invN - mu * mu + EPS_BN);
        r.z = hv.z + fmaxf(gm.z * (xv.z - mu) * inv + bt.z, 0.f);
    }
    {
        float mu = cs.w * invN;
        float inv = rsqrtf(cq.w * invN - mu * mu + EPS_BN);
        r.w = hv.w + fmaxf(gm.w * (xv.w - mu) * inv + bt.w, 0.f);
    }
    ((float4*)out)[i] = r;
}

// ---------------- launch ------------------------------------------------------------
extern "C" void kernel_launch(void* const* d_in, const int* in_sizes, int n_in,
                              void* d_out, int out_size) {
    const float* h     = (const float*)d_in[0];
    const int*   src   = (const int*)d_in[1];
    const int*   dst   = (const int*)d_in[2];
    const float* W     = (const float*)d_in[3];
    const float* b     = (const float*)d_in[4];
    const float* gamma = (const float*)d_in[5];
    const float* beta  = (const float*)d_in[6];
    float* out = (float*)d_out;

    cudaFuncSetAttribute(k_gemm_mma, cudaFuncAttributeMaxDynamicSharedMemorySize, SMEM_MM);

    k_hist_wprep<<<(N_EDGES / 4 + 255) / 256, 256>>>(dst, W);
    k_scan<<<NB, 256>>>();
    k_scatter<<<(N_EDGES / 4 + 255) / 256, 256>>>(src, dst);
    k_agg<<<(N_NODES + 7) / 8, 256>>>(h);
    k_gemm_mma<<<(N_NODES + 127) / 128, 256, SMEM_MM>>>(b);
    k_final<<<(N_NODES * F_DIM / 4 + 255) / 256, 256>>>(h, gamma, beta, out);
}

// round 11
// speedup vs baseline: 1.2452x; 1.0795x over previous
#include <cuda_runtime.h>
#include <cuda_fp16.h>
#include <math.h>
#include <stdint.h>

#define N_NODES 50000
#define N_EDGES 800000
#define F_DIM   64
#define AVG_D_LOG 2.833f
#define EPS_STD 1e-5f
#define EPS_BN  1e-5f
#define NB 196   // ceil(50000/256)
#define A_FLAG 0x40000000u
#define P_FLAG 0x80000000u

typedef unsigned long long ull;

// ---------------- device scratch (all zero-initialized at load) ----------------
__device__ int   g_deg[N_NODES];       // zeroed by k_agg after use
__device__ int   g_off[N_NODES];
__device__ int   g_cursor[N_NODES];
__device__ int   g_esrc[N_EDGES];
__device__ unsigned g_pkt[NB];         // scan lookback state; zeroed by k_agg
__device__ unsigned g_a16[(size_t)N_NODES * 128];  // agg rows as fp16x2 words
__device__ float g_c1[N_NODES];
__device__ float g_c2[N_NODES];
__device__ float g_x[(size_t)N_NODES * F_DIM];
__device__ float g_colsum[F_DIM];
__device__ float g_colsq[F_DIM];
__device__ __half g_whi[64 * 768];     // W^T hi split [n][k]
__device__ __half g_wlo[64 * 768];     // W^T lo residual

// ---------------- helpers -------------------------------------------------------
__device__ __forceinline__ uint32_t smem_u32(const void* p) {
    uint32_t r;
    asm("{ .reg .u64 t; cvta.to.shared.u64 t, %1; cvt.u32.u64 %0, t; }"
        : "=r"(r) : "l"(p));
    return r;
}
__device__ __forceinline__ void ldsm4(uint32_t& r0, uint32_t& r1,
                                      uint32_t& r2, uint32_t& r3, uint32_t a) {
    asm volatile("ldmatrix.sync.aligned.m8n8.x4.shared.b16 {%0,%1,%2,%3}, [%4];"
                 : "=r"(r0), "=r"(r1), "=r"(r2), "=r"(r3) : "r"(a));
}
__device__ __forceinline__ void mma_f16(float* d,
                                        uint32_t a0, uint32_t a1, uint32_t a2, uint32_t a3,
                                        uint32_t b0, uint32_t b1) {
    asm volatile(
        "mma.sync.aligned.m16n8k16.row.col.f32.f16.f16.f32 "
        "{%0,%1,%2,%3}, {%4,%5,%6,%7}, {%8,%9}, {%0,%1,%2,%3};"
        : "+f"(d[0]), "+f"(d[1]), "+f"(d[2]), "+f"(d[3])
        : "r"(a0), "r"(a1), "r"(a2), "r"(a3), "r"(b0), "r"(b1));
}
__device__ __forceinline__ uint32_t packh(float x, float y) {
    __half2 t;
    t.x = __float2half_rn(x);
    t.y = __float2half_rn(y);
    return *(uint32_t*)&t;
}
// packed f32x2 (add/fma only on this toolchain)
__device__ __forceinline__ void add2(ull& d, ull a) {
    asm("add.rn.f32x2 %0, %0, %1;" : "+l"(d) : "l"(a));
}
__device__ __forceinline__ void fma2(ull& d, ull a) {
    asm("fma.rn.f32x2 %0, %1, %1, %0;" : "+l"(d) : "l"(a));
}
__device__ __forceinline__ float lo32(ull v) { return __uint_as_float((unsigned)v); }
__device__ __forceinline__ float hi32(ull v) { return __uint_as_float((unsigned)(v >> 32)); }

// ---------------- K1: degree histogram (int4) + W fp16 split ---------------------
__global__ void k_hist_wprep(const int* __restrict__ dst, const float* __restrict__ W) {
    int t = blockIdx.x * blockDim.x + threadIdx.x;
    if (t < N_EDGES / 4) {
        int4 d4 = ((const int4*)dst)[t];
        atomicAdd(&g_deg[d4.x], 1);
        atomicAdd(&g_deg[d4.y], 1);
        atomicAdd(&g_deg[d4.z], 1);
        atomicAdd(&g_deg[d4.w], 1);
    }
    if (t < 768 * 64) {
        int k = t >> 6;
        int n = t & 63;
        float w = W[t];
        __half wh = __float2half_rn(w);
        __half wl = __float2half_rn(w - __half2float(wh));
        g_whi[n * 768 + k] = wh;
        g_wlo[n * 768 + k] = wl;
    }
}

// ---------------- K2: single-pass decoupled-lookback scan -------------------------
__global__ void k_scan(void) {
    __shared__ int s[256];
    __shared__ unsigned sprefix;
    int t = threadIdx.x;
    int bidx = blockIdx.x;
    int i = bidx * 256 + t;
    int v = (i < N_NODES) ? g_deg[i] : 0;
    s[t] = v;
    __syncthreads();
    #pragma unroll
    for (int off = 1; off < 256; off <<= 1) {
        int x = (t >= off) ? s[t - off] : 0;
        __syncthreads();
        s[t] += x;
        __syncthreads();
    }
    int total = s[255];

    if (t == 0) {
        unsigned pub = (bidx == 0) ? (P_FLAG | (unsigned)total)
                                   : (A_FLAG | (unsigned)total);
        atomicExch(&g_pkt[bidx], pub);
        if (bidx == 0) sprefix = 0;
    }

    if (bidx > 0 && t < 32) {
        unsigned running = 0;
        int idx = bidx - 1;
        for (;;) {
            int j = idx - t;
            unsigned p;
            if (j >= 0) {
                do { p = ((volatile unsigned*)g_pkt)[j]; } while (p == 0);
            } else {
                p = P_FLAG;
            }
            unsigned pm = __ballot_sync(0xffffffffu, (p & P_FLAG) != 0);
            unsigned val = p & 0x3fffffffu;
            if (pm) {
                int k = __ffs(pm) - 1;
                unsigned contrib = (t <= k) ? val : 0;
                #pragma unroll
                for (int o = 16; o > 0; o >>= 1)
                    contrib += __shfl_down_sync(0xffffffffu, contrib, o);
                if (t == 0) sprefix = running + contrib;
                break;
            } else {
                unsigned contrib = (j >= 0) ? val : 0;
                #pragma unroll
                for (int o = 16; o > 0; o >>= 1)
                    contrib += __shfl_down_sync(0xffffffffu, contrib, o);
                running += __shfl_sync(0xffffffffu, contrib, 0);
                idx -= 32;
            }
        }
        if (t == 0)
            atomicExch(&g_pkt[bidx], P_FLAG | (sprefix + (unsigned)total));
    }
    __syncthreads();

    if (i < N_NODES) {
        int ex = (int)sprefix + s[t] - v;
        g_off[i] = ex;
        g_cursor[i] = ex;
    }
}

// ---------------- K3: scatter edges, 4 per thread (MLP=4) -------------------------
__global__ void k_scatter(const int* __restrict__ src, const int* __restrict__ dst) {
    int t = blockIdx.x * blockDim.x + threadIdx.x;
    if (t >= N_EDGES / 4) return;
    int4 d4 = ((const int4*)dst)[t];
    int4 s4 = ((const int4*)src)[t];
    int p0 = atomicAdd(&g_cursor[d4.x], 1);
    int p1 = atomicAdd(&g_cursor[d4.y], 1);
    int p2 = atomicAdd(&g_cursor[d4.z], 1);
    int p3 = atomicAdd(&g_cursor[d4.w], 1);
    g_esrc[p0] = s4.x;
    g_esrc[p1] = s4.y;
    g_esrc[p2] = s4.z;
    g_esrc[p3] = s4.w;
}

// ---------------- K4: warp-per-node aggregation (single banks, regs=32) -----------
__global__ void k_agg(const float* __restrict__ h) {
    if (blockIdx.x == 0) {
        int tt = threadIdx.x;
        if (tt < F_DIM) { g_colsum[tt] = 0.f; g_colsq[tt] = 0.f; }
        if (tt < NB) g_pkt[tt] = 0u;
    }

    int warp = (blockIdx.x * blockDim.x + threadIdx.x) >> 5;
    int lane = threadIdx.x & 31;
    if (warp >= N_NODES) return;

    int start = g_off[warp];
    int d = g_deg[warp];
    int end = start + d;

    const ull* hl = (const ull*)h + lane;

    ull sum = 0ull;
    ull sq  = 0ull;
    float mx0 = -3.402823466e38f, mx1 = -3.402823466e38f;
    float mn0 =  3.402823466e38f, mn1 =  3.402823466e38f;

    int e = start;
    while (e < end && (e & 3)) {
        ull va = hl[g_esrc[e] * 32];
        add2(sum, va); fma2(sq, va);
        mx0 = fmaxf(mx0, lo32(va)); mx1 = fmaxf(mx1, hi32(va));
        mn0 = fminf(mn0, lo32(va)); mn1 = fminf(mn1, hi32(va));
        e++;
    }
    for (; e + 4 <= end; e += 4) {
        int4 s4 = *(const int4*)(g_esrc + e);
        ull va = hl[s4.x * 32];
        ull vb = hl[s4.y * 32];
        ull vc = hl[s4.z * 32];
        ull vd = hl[s4.w * 32];
        add2(sum, va); fma2(sq, va);
        mx0 = fmaxf(mx0, lo32(va)); mx1 = fmaxf(mx1, hi32(va));
        mn0 = fminf(mn0, lo32(va)); mn1 = fminf(mn1, hi32(va));
        add2(sum, vb); fma2(sq, vb);
        mx0 = fmaxf(mx0, lo32(vb)); mx1 = fmaxf(mx1, hi32(vb));
        mn0 = fminf(mn0, lo32(vb)); mn1 = fminf(mn1, hi32(vb));
        add2(sum, vc); fma2(sq, vc);
        mx0 = fmaxf(mx0, lo32(vc)); mx1 = fmaxf(mx1, hi32(vc));
        mn0 = fminf(mn0, lo32(vc)); mn1 = fminf(mn1, hi32(vc));
        add2(sum, vd); fma2(sq, vd);
        mx0 = fmaxf(mx0, lo32(vd)); mx1 = fmaxf(mx1, hi32(vd));
        mn0 = fminf(mn0, lo32(vd)); mn1 = fminf(mn1, hi32(vd));
    }
    for (; e < end; e++) {
        ull va = hl[g_esrc[e] * 32];
        add2(sum, va); fma2(sq, va);
        mx0 = fmaxf(mx0, lo32(va)); mx1 = fmaxf(mx1, hi32(va));
        mn0 = fminf(mn0, lo32(va)); mn1 = fminf(mn1, hi32(va));
    }

    unsigned* ar = g_a16 + (size_t)warp * 128 + lane;
    if (d > 0) {
        float inv = 1.0f / (float)d;
        float s0 = lo32(sum), s1 = hi32(sum);
        float q0 = lo32(sq),  q1 = hi32(sq);
        float mean0 = s0 * inv, mean1 = s1 * inv;
        float var0 = fmaxf(q0 * inv - mean0 * mean0, 0.f);
        float var1 = fmaxf(q1 * inv - mean1 * mean1, 0.f);
        float std0 = sqrtf(var0 + EPS_STD);
        float std1 = sqrtf(var1 + EPS_STD);
        // sections: 0=mean 1=max 2=min 3=std; 32 fp16x2 words each
        ar[0]  = packh(mean0, mean1);
        ar[32] = packh(mx0, mx1);
        ar[64] = packh(mn0, mn1);
        ar[96] = packh(std0, std1);
        if (lane == 0) {
            float logD = logf((float)d + 1.0f);
            g_c1[warp] = logD / AVG_D_LOG;
            g_c2[warp] = AVG_D_LOG / fmaxf(logD, 1e-12f);
        }
    } else {
        ar[0] = 0u; ar[32] = 0u; ar[64] = 0u; ar[96] = 0u;
        if (lane == 0) { g_c1[warp] = 0.f; g_c2[warp] = 0.f; }
    }
    if (lane == 0) g_deg[warp] = 0;
}

// ---------------- K5: mma.sync fp16 GEMM (A single fp16, W hi/lo) -----------------
// D_p = A @ (Wph + Wpl), fp32 accum; 2 MMA terms.
#define AST 144
#define SA    0
#define SB    (128 * AST)             // 18432
#define SBUF  (64 * AST)              // 9216
#define SMEM_MM (SB + 6 * SBUF)       // 73728

__global__ void __launch_bounds__(256)
k_gemm_mma(const float* __restrict__ bias) {
    extern __shared__ char smem[];
    const uint32_t sb = smem_u32(smem);
    int t = threadIdx.x;
    int w = t >> 5;
    int lane = t & 31;
    int m0 = blockIdx.x * 128;

    float acc[3][8][4];
    #pragma unroll
    for (int p = 0; p < 3; p++)
        #pragma unroll
        for (int nt = 0; nt < 8; nt++)
            #pragma unroll
            for (int j = 0; j < 4; j++) acc[p][nt][j] = 0.f;

    for (int c = 0; c < 4; c++) {
        __syncthreads();
        // ---- A chunk: direct fp16 copy (section c of each node row) ----
        #pragma unroll
        for (int it = 0; it < 4; it++) {
            int idx = t + it * 256;       // 0..1023
            int row = idx >> 3;
            int g = idx & 7;
            int gm = m0 + row;
            uint4 v = make_uint4(0, 0, 0, 0);
            if (gm < N_NODES)
                v = *(const uint4*)(g_a16 + (size_t)gm * 128 + c * 32 + g * 4);
            *(uint4*)(smem + SA + row * AST + g * 16) = v;
        }
        // ---- B chunk: 6 bufs (p0h,p0l,p1h,p1l,p2h,p2l), 64 n-rows x 64 k ----
        #pragma unroll
        for (int it = 0; it < 12; it++) {
            int idx = t + it * 256;
            int buf = idx >> 9;
            int rem = idx & 511;
            int row = rem >> 3;
            int g = rem & 7;
            int p = buf >> 1;
            const __half* srcp = ((buf & 1) ? g_wlo : g_whi)
                                 + row * 768 + p * 256 + c * 64 + g * 8;
            *(uint4*)(smem + SB + buf * SBUF + row * AST + g * 16) =
                *(const uint4*)srcp;
        }
        __syncthreads();

        #pragma unroll
        for (int ks = 0; ks < 4; ks++) {
            int arow = w * 16 + (lane & 15);
            uint32_t aoff = (uint32_t)(arow * AST + ks * 32 + ((lane >> 4) << 4));
            uint32_t a0, a1, a2, a3;
            ldsm4(a0, a1, a2, a3, sb + SA + aoff);

            #pragma unroll
            for (int np = 0; np < 4; np++) {
                int nrow = np * 16 + (lane & 7) + ((lane & 16) ? 8 : 0);
                uint32_t boff = (uint32_t)(nrow * AST + ks * 32 + ((lane & 8) ? 16 : 0));
                #pragma unroll
                for (int p = 0; p < 3; p++) {
                    uint32_t bh0, bh1, bh2, bh3, bl0, bl1, bl2, bl3;
                    ldsm4(bh0, bh1, bh2, bh3, sb + SB + (2 * p)     * SBUF + boff);
                    ldsm4(bl0, bl1, bl2, bl3, sb + SB + (2 * p + 1) * SBUF + boff);
                    float* d0 = acc[p][np * 2];
                    float* d1 = acc[p][np * 2 + 1];
                    mma_f16(d0, a0, a1, a2, a3, bh0, bh1);
                    mma_f16(d0, a0, a1, a2, a3, bl0, bl1);
                    mma_f16(d1, a0, a1, a2, a3, bh2, bh3);
                    mma_f16(d1, a0, a1, a2, a3, bl2, bl3);
                }
            }
        }
    }

    __syncthreads();
    float* swsum = (float*)smem;
    float* swsq  = (float*)(smem + 2048);

    int rowA = m0 + w * 16 + (lane >> 2);
    int rowB = rowA + 8;
    bool va = rowA < N_NODES, vb = rowB < N_NODES;
    float c1a = 0.f, c2a = 0.f, c1b = 0.f, c2b = 0.f;
    if (va) { c1a = g_c1[rowA]; c2a = g_c2[rowA]; }
    if (vb) { c1b = g_c1[rowB]; c2b = g_c2[rowB]; }

    #pragma unroll
    for (int nt = 0; nt < 8; nt++) {
        int col = nt * 8 + (lane & 3) * 2;
        float b0 = bias[col];
        float b1 = bias[col + 1];
        float x0a = acc[0][nt][0] + c1a * acc[1][nt][0] + c2a * acc[2][nt][0] + b0;
        float x1a = acc[0][nt][1] + c1a * acc[1][nt][1] + c2a * acc[2][nt][1] + b1;
        float x0b = acc[0][nt][2] + c1b * acc[1][nt][2] + c2b * acc[2][nt][2] + b0;
        float x1b = acc[0][nt][3] + c1b * acc[1][nt][3] + c2b * acc[2][nt][3] + b1;
        if (va) *(float2*)(g_x + (size_t)rowA * 64 + col) = make_float2(x0a, x1a);
        if (vb) *(float2*)(g_x + (size_t)rowB * 64 + col) = make_float2(x0b, x1b);

        float s0 = (va ? x0a : 0.f) + (vb ? x0b : 0.f);
        float s1 = (va ? x1a : 0.f) + (vb ? x1b : 0.f);
        float q0 = (va ? x0a * x0a : 0.f) + (vb ? x0b * x0b : 0.f);
        float q1 = (va ? x1a * x1a : 0.f) + (vb ? x1b * x1b : 0.f);
        #pragma unroll
        for (int o = 4; o <= 16; o <<= 1) {
            s0 += __shfl_xor_sync(0xffffffffu, s0, o);
            s1 += __shfl_xor_sync(0xffffffffu, s1, o);
            q0 += __shfl_xor_sync(0xffffffffu, q0, o);
            q1 += __shfl_xor_sync(0xffffffffu, q1, o);
        }
        if (lane < 4) {
            swsum[w * 64 + nt * 8 + lane * 2]     = s0;
            swsum[w * 64 + nt * 8 + lane * 2 + 1] = s1;
            swsq [w * 64 + nt * 8 + lane * 2]     = q0;
            swsq [w * 64 + nt * 8 + lane * 2 + 1] = q1;
        }
    }
    __syncthreads();
    if (t < 64) {
        float s = 0.f, q = 0.f;
        #pragma unroll
        for (int k = 0; k < 8; k++) {
            s += swsum[k * 64 + t];
            q += swsq[k * 64 + t];
        }
        atomicAdd(&g_colsum[t], s);
        atomicAdd(&g_colsq[t], q);
    }
}

// ---------------- K6: BN + ReLU + residual (float4) -------------------------------
__global__ void k_final(const float* __restrict__ h,
                        const float* __restrict__ gamma,
                        const float* __restrict__ beta,
                        float* __restrict__ out) {
    int i = blockIdx.x * blockDim.x + threadIdx.x;
    if (i >= N_NODES * F_DIM / 4) return;
    int j = (i & 15) * 4;
    const float invN = 1.0f / (float)N_NODES;
    float4 cs = *(const float4*)(g_colsum + j);
    float4 cq = *(const float4*)(g_colsq + j);
    float4 gm = *(const float4*)(gamma + j);
    float4 bt = *(const float4*)(beta + j);
    float4 xv = ((const float4*)g_x)[i];
    float4 hv = ((const float4*)h)[i];
    float4 r;
    {
        float mu = cs.x * invN;
        float inv = rsqrtf(cq.x * invN - mu * mu + EPS_BN);
        r.x = hv.x + fmaxf(gm.x * (xv.x - mu) * inv + bt.x, 0.f);
    }
    {
        float mu = cs.y * invN;
        float inv = rsqrtf(cq.y * invN - mu * mu + EPS_BN);
        r.y = hv.y + fmaxf(gm.y * (xv.y - mu) * inv + bt.y, 0.f);
    }
    {
        float mu = cs.z * invN;
        float inv = rsqrtf(cq.z * invN - mu * mu + EPS_BN);
        r.z = hv.z + fmaxf(gm.z * (xv.z - mu) * inv + bt.z, 0.f);
    }
    {
        float mu = cs.w * invN;
        float inv = rsqrtf(cq.w * invN - mu * mu + EPS_BN);
        r.w = hv.w + fmaxf(gm.w * (xv.w - mu) * inv + bt.w, 0.f);
    }
    ((float4*)out)[i] = r;
}

// ---------------- launch ------------------------------------------------------------
extern "C" void kernel_launch(void* const* d_in, const int* in_sizes, int n_in,
                              void* d_out, int out_size) {
    const float* h     = (const float*)d_in[0];
    const int*   src   = (const int*)d_in[1];
    const int*   dst   = (const int*)d_in[2];
    const float* W     = (const float*)d_in[3];
    const float* b     = (const float*)d_in[4];
    const float* gamma = (const float*)d_in[5];
    const float* beta  = (const float*)d_in[6];
    float* out = (float*)d_out;

    cudaFuncSetAttribute(k_gemm_mma, cudaFuncAttributeMaxDynamicSharedMemorySize, SMEM_MM);

    k_hist_wprep<<<(N_EDGES / 4 + 255) / 256, 256>>>(dst, W);
    k_scan<<<NB, 256>>>();
    k_scatter<<<(N_EDGES / 4 + 255) / 256, 256>>>(src, dst);
    k_agg<<<(N_NODES + 7) / 8, 256>>>(h);
    k_gemm_mma<<<(N_NODES + 127) / 128, 256, SMEM_MM>>>(b);
    k_final<<<(N_NODES * F_DIM / 4 + 255) / 256, 256>>>(h, gamma, beta, out);
}

// round 12
// speedup vs baseline: 1.3603x; 1.0924x over previous
#include <cuda_runtime.h>
#include <cuda_fp16.h>
#include <math.h>
#include <stdint.h>

#define N_NODES 50000
#define N_EDGES 800000
#define F_DIM   64
#define AVG_D_LOG 2.833f
#define EPS_STD 1e-5f
#define EPS_BN  1e-5f
#define NB 196   // ceil(50000/256)
#define A_FLAG 0x40000000u
#define P_FLAG 0x80000000u

typedef unsigned long long ull;

// ---------------- device scratch (all zero-initialized at load) ----------------
__device__ int   g_deg[N_NODES];       // zeroed by k_agg after use
__device__ int   g_off[N_NODES];
__device__ int   g_cursor[N_NODES];
__device__ int   g_esrc[N_EDGES];
__device__ unsigned g_pkt[NB];         // scan lookback state; zeroed by k_agg
__device__ unsigned g_a16[(size_t)N_NODES * 128];  // agg rows as fp16x2 words
__device__ float g_c1[N_NODES];
__device__ float g_c2[N_NODES];
__device__ float g_x[(size_t)N_NODES * F_DIM];
__device__ float g_colsum[F_DIM];
__device__ float g_colsq[F_DIM];
__device__ __half g_whi[64 * 768];     // W^T fp16 [n][k]

// ---------------- helpers -------------------------------------------------------
__device__ __forceinline__ uint32_t smem_u32(const void* p) {
    uint32_t r;
    asm("{ .reg .u64 t; cvta.to.shared.u64 t, %1; cvt.u32.u64 %0, t; }"
        : "=r"(r) : "l"(p));
    return r;
}
__device__ __forceinline__ void ldsm4(uint32_t& r0, uint32_t& r1,
                                      uint32_t& r2, uint32_t& r3, uint32_t a) {
    asm volatile("ldmatrix.sync.aligned.m8n8.x4.shared.b16 {%0,%1,%2,%3}, [%4];"
                 : "=r"(r0), "=r"(r1), "=r"(r2), "=r"(r3) : "r"(a));
}
__device__ __forceinline__ void mma_f16(float* d,
                                        uint32_t a0, uint32_t a1, uint32_t a2, uint32_t a3,
                                        uint32_t b0, uint32_t b1) {
    asm volatile(
        "mma.sync.aligned.m16n8k16.row.col.f32.f16.f16.f32 "
        "{%0,%1,%2,%3}, {%4,%5,%6,%7}, {%8,%9}, {%0,%1,%2,%3};"
        : "+f"(d[0]), "+f"(d[1]), "+f"(d[2]), "+f"(d[3])
        : "r"(a0), "r"(a1), "r"(a2), "r"(a3), "r"(b0), "r"(b1));
}
__device__ __forceinline__ uint32_t packh(float x, float y) {
    __half2 t;
    t.x = __float2half_rn(x);
    t.y = __float2half_rn(y);
    return *(uint32_t*)&t;
}
// packed f32x2 (add/fma only on this toolchain)
__device__ __forceinline__ void add2(ull& d, ull a) {
    asm("add.rn.f32x2 %0, %0, %1;" : "+l"(d) : "l"(a));
}
__device__ __forceinline__ void fma2(ull& d, ull a) {
    asm("fma.rn.f32x2 %0, %1, %1, %0;" : "+l"(d) : "l"(a));
}
__device__ __forceinline__ float lo32(ull v) { return __uint_as_float((unsigned)v); }
__device__ __forceinline__ float hi32(ull v) { return __uint_as_float((unsigned)(v >> 32)); }

// ---------------- K1: degree histogram (int4) + W fp16 transpose ------------------
__global__ void k_hist_wprep(const int* __restrict__ dst, const float* __restrict__ W) {
    int t = blockIdx.x * blockDim.x + threadIdx.x;
    if (t < N_EDGES / 4) {
        int4 d4 = ((const int4*)dst)[t];
        atomicAdd(&g_deg[d4.x], 1);
        atomicAdd(&g_deg[d4.y], 1);
        atomicAdd(&g_deg[d4.z], 1);
        atomicAdd(&g_deg[d4.w], 1);
    }
    if (t < 768 * 64) {
        int k = t >> 6;
        int n = t & 63;
        g_whi[n * 768 + k] = __float2half_rn(W[t]);
    }
}

// ---------------- K2: single-pass decoupled-lookback scan -------------------------
__global__ void k_scan(void) {
    __shared__ int s[256];
    __shared__ unsigned sprefix;
    int t = threadIdx.x;
    int bidx = blockIdx.x;
    int i = bidx * 256 + t;
    int v = (i < N_NODES) ? g_deg[i] : 0;
    s[t] = v;
    __syncthreads();
    #pragma unroll
    for (int off = 1; off < 256; off <<= 1) {
        int x = (t >= off) ? s[t - off] : 0;
        __syncthreads();
        s[t] += x;
        __syncthreads();
    }
    int total = s[255];

    if (t == 0) {
        unsigned pub = (bidx == 0) ? (P_FLAG | (unsigned)total)
                                   : (A_FLAG | (unsigned)total);
        atomicExch(&g_pkt[bidx], pub);
        if (bidx == 0) sprefix = 0;
    }

    if (bidx > 0 && t < 32) {
        unsigned running = 0;
        int idx = bidx - 1;
        for (;;) {
            int j = idx - t;
            unsigned p;
            if (j >= 0) {
                do { p = ((volatile unsigned*)g_pkt)[j]; } while (p == 0);
            } else {
                p = P_FLAG;
            }
            unsigned pm = __ballot_sync(0xffffffffu, (p & P_FLAG) != 0);
            unsigned val = p & 0x3fffffffu;
            if (pm) {
                int k = __ffs(pm) - 1;
                unsigned contrib = (t <= k) ? val : 0;
                #pragma unroll
                for (int o = 16; o > 0; o >>= 1)
                    contrib += __shfl_down_sync(0xffffffffu, contrib, o);
                if (t == 0) sprefix = running + contrib;
                break;
            } else {
                unsigned contrib = (j >= 0) ? val : 0;
                #pragma unroll
                for (int o = 16; o > 0; o >>= 1)
                    contrib += __shfl_down_sync(0xffffffffu, contrib, o);
                running += __shfl_sync(0xffffffffu, contrib, 0);
                idx -= 32;
            }
        }
        if (t == 0)
            atomicExch(&g_pkt[bidx], P_FLAG | (sprefix + (unsigned)total));
    }
    __syncthreads();

    if (i < N_NODES) {
        int ex = (int)sprefix + s[t] - v;
        g_off[i] = ex;
        g_cursor[i] = ex;
    }
}

// ---------------- K3: scatter edges, 4 per thread (MLP=4) -------------------------
__global__ void k_scatter(const int* __restrict__ src, const int* __restrict__ dst) {
    int t = blockIdx.x * blockDim.x + threadIdx.x;
    if (t >= N_EDGES / 4) return;
    int4 d4 = ((const int4*)dst)[t];
    int4 s4 = ((const int4*)src)[t];
    int p0 = atomicAdd(&g_cursor[d4.x], 1);
    int p1 = atomicAdd(&g_cursor[d4.y], 1);
    int p2 = atomicAdd(&g_cursor[d4.z], 1);
    int p3 = atomicAdd(&g_cursor[d4.w], 1);
    g_esrc[p0] = s4.x;
    g_esrc[p1] = s4.y;
    g_esrc[p2] = s4.z;
    g_esrc[p3] = s4.w;
}

// ---------------- K4: warp-per-node aggregation (single banks, regs=32) -----------
__global__ void k_agg(const float* __restrict__ h) {
    if (blockIdx.x == 0) {
        int tt = threadIdx.x;
        if (tt < F_DIM) { g_colsum[tt] = 0.f; g_colsq[tt] = 0.f; }
        if (tt < NB) g_pkt[tt] = 0u;
    }

    int warp = (blockIdx.x * blockDim.x + threadIdx.x) >> 5;
    int lane = threadIdx.x & 31;
    if (warp >= N_NODES) return;

    int start = g_off[warp];
    int d = g_deg[warp];
    int end = start + d;

    const ull* hl = (const ull*)h + lane;

    ull sum = 0ull;
    ull sq  = 0ull;
    float mx0 = -3.402823466e38f, mx1 = -3.402823466e38f;
    float mn0 =  3.402823466e38f, mn1 =  3.402823466e38f;

    int e = start;
    while (e < end && (e & 3)) {
        ull va = hl[g_esrc[e] * 32];
        add2(sum, va); fma2(sq, va);
        mx0 = fmaxf(mx0, lo32(va)); mx1 = fmaxf(mx1, hi32(va));
        mn0 = fminf(mn0, lo32(va)); mn1 = fminf(mn1, hi32(va));
        e++;
    }
    for (; e + 4 <= end; e += 4) {
        int4 s4 = *(const int4*)(g_esrc + e);
        ull va = hl[s4.x * 32];
        ull vb = hl[s4.y * 32];
        ull vc = hl[s4.z * 32];
        ull vd = hl[s4.w * 32];
        add2(sum, va); fma2(sq, va);
        mx0 = fmaxf(mx0, lo32(va)); mx1 = fmaxf(mx1, hi32(va));
        mn0 = fminf(mn0, lo32(va)); mn1 = fminf(mn1, hi32(va));
        add2(sum, vb); fma2(sq, vb);
        mx0 = fmaxf(mx0, lo32(vb)); mx1 = fmaxf(mx1, hi32(vb));
        mn0 = fminf(mn0, lo32(vb)); mn1 = fminf(mn1, hi32(vb));
        add2(sum, vc); fma2(sq, vc);
        mx0 = fmaxf(mx0, lo32(vc)); mx1 = fmaxf(mx1, hi32(vc));
        mn0 = fminf(mn0, lo32(vc)); mn1 = fminf(mn1, hi32(vc));
        add2(sum, vd); fma2(sq, vd);
        mx0 = fmaxf(mx0, lo32(vd)); mx1 = fmaxf(mx1, hi32(vd));
        mn0 = fminf(mn0, lo32(vd)); mn1 = fminf(mn1, hi32(vd));
    }
    for (; e < end; e++) {
        ull va = hl[g_esrc[e] * 32];
        add2(sum, va); fma2(sq, va);
        mx0 = fmaxf(mx0, lo32(va)); mx1 = fmaxf(mx1, hi32(va));
        mn0 = fminf(mn0, lo32(va)); mn1 = fminf(mn1, hi32(va));
    }

    unsigned* ar = g_a16 + (size_t)warp * 128 + lane;
    if (d > 0) {
        float inv = 1.0f / (float)d;
        float s0 = lo32(sum), s1 = hi32(sum);
        float q0 = lo32(sq),  q1 = hi32(sq);
        float mean0 = s0 * inv, mean1 = s1 * inv;
        float var0 = fmaxf(q0 * inv - mean0 * mean0, 0.f);
        float var1 = fmaxf(q1 * inv - mean1 * mean1, 0.f);
        float std0 = sqrtf(var0 + EPS_STD);
        float std1 = sqrtf(var1 + EPS_STD);
        // sections: 0=mean 1=max 2=min 3=std; 32 fp16x2 words each
        ar[0]  = packh(mean0, mean1);
        ar[32] = packh(mx0, mx1);
        ar[64] = packh(mn0, mn1);
        ar[96] = packh(std0, std1);
        if (lane == 0) {
            float logD = logf((float)d + 1.0f);
            g_c1[warp] = logD / AVG_D_LOG;
            g_c2[warp] = AVG_D_LOG / fmaxf(logD, 1e-12f);
        }
    } else {
        ar[0] = 0u; ar[32] = 0u; ar[64] = 0u; ar[96] = 0u;
        if (lane == 0) { g_c1[warp] = 0.f; g_c2[warp] = 0.f; }
    }
    if (lane == 0) g_deg[warp] = 0;
}

// ---------------- K5: mma.sync fp16 GEMM (A fp16, W fp16 single term) --------------
#define AST 144
#define SA    0
#define SB    (128 * AST)             // 18432
#define SBUF  (64 * AST)              // 9216
#define SMEM_MM (SB + 3 * SBUF)       // 46080

__global__ void __launch_bounds__(256)
k_gemm_mma(const float* __restrict__ bias) {
    extern __shared__ char smem[];
    const uint32_t sb = smem_u32(smem);
    int t = threadIdx.x;
    int w = t >> 5;
    int lane = t & 31;
    int m0 = blockIdx.x * 128;

    float acc[3][8][4];
    #pragma unroll
    for (int p = 0; p < 3; p++)
        #pragma unroll
        for (int nt = 0; nt < 8; nt++)
            #pragma unroll
            for (int j = 0; j < 4; j++) acc[p][nt][j] = 0.f;

    for (int c = 0; c < 4; c++) {
        __syncthreads();
        // ---- A chunk: direct fp16 copy (section c of each node row) ----
        #pragma unroll
        for (int it = 0; it < 4; it++) {
            int idx = t + it * 256;       // 0..1023
            int row = idx >> 3;
            int g = idx & 7;
            int gm = m0 + row;
            uint4 v = make_uint4(0, 0, 0, 0);
            if (gm < N_NODES)
                v = *(const uint4*)(g_a16 + (size_t)gm * 128 + c * 32 + g * 4);
            *(uint4*)(smem + SA + row * AST + g * 16) = v;
        }
        // ---- B chunk: 3 panels, 64 n-rows x 64 k fp16 ----
        #pragma unroll
        for (int it = 0; it < 6; it++) {
            int idx = t + it * 256;       // 0..1535
            int p = idx >> 9;
            int rem = idx & 511;
            int row = rem >> 3;
            int g = rem & 7;
            const __half* srcp = g_whi + row * 768 + p * 256 + c * 64 + g * 8;
            *(uint4*)(smem + SB + p * SBUF + row * AST + g * 16) =
                *(const uint4*)srcp;
        }
        __syncthreads();

        #pragma unroll
        for (int ks = 0; ks < 4; ks++) {
            int arow = w * 16 + (lane & 15);
            uint32_t aoff = (uint32_t)(arow * AST + ks * 32 + ((lane >> 4) << 4));
            uint32_t a0, a1, a2, a3;
            ldsm4(a0, a1, a2, a3, sb + SA + aoff);

            #pragma unroll
            for (int np = 0; np < 4; np++) {
                int nrow = np * 16 + (lane & 7) + ((lane & 16) ? 8 : 0);
                uint32_t boff = (uint32_t)(nrow * AST + ks * 32 + ((lane & 8) ? 16 : 0));
                #pragma unroll
                for (int p = 0; p < 3; p++) {
                    uint32_t b0, b1, b2, b3;
                    ldsm4(b0, b1, b2, b3, sb + SB + p * SBUF + boff);
                    mma_f16(acc[p][np * 2],     a0, a1, a2, a3, b0, b1);
                    mma_f16(acc[p][np * 2 + 1], a0, a1, a2, a3, b2, b3);
                }
            }
        }
    }

    __syncthreads();
    float* swsum = (float*)smem;
    float* swsq  = (float*)(smem + 2048);

    int rowA = m0 + w * 16 + (lane >> 2);
    int rowB = rowA + 8;
    bool va = rowA < N_NODES, vb = rowB < N_NODES;
    float c1a = 0.f, c2a = 0.f, c1b = 0.f, c2b = 0.f;
    if (va) { c1a = g_c1[rowA]; c2a = g_c2[rowA]; }
    if (vb) { c1b = g_c1[rowB]; c2b = g_c2[rowB]; }

    #pragma unroll
    for (int nt = 0; nt < 8; nt++) {
        int col = nt * 8 + (lane & 3) * 2;
        float b0 = bias[col];
        float b1 = bias[col + 1];
        float x0a = acc[0][nt][0] + c1a * acc[1][nt][0] + c2a * acc[2][nt][0] + b0;
        float x1a = acc[0][nt][1] + c1a * acc[1][nt][1] + c2a * acc[2][nt][1] + b1;
        float x0b = acc[0][nt][2] + c1b * acc[1][nt][2] + c2b * acc[2][nt][2] + b0;
        float x1b = acc[0][nt][3] + c1b * acc[1][nt][3] + c2b * acc[2][nt][3] + b1;
        if (va) *(float2*)(g_x + (size_t)rowA * 64 + col) = make_float2(x0a, x1a);
        if (vb) *(float2*)(g_x + (size_t)rowB * 64 + col) = make_float2(x0b, x1b);

        float s0 = (va ? x0a : 0.f) + (vb ? x0b : 0.f);
        float s1 = (va ? x1a : 0.f) + (vb ? x1b : 0.f);
        float q0 = (va ? x0a * x0a : 0.f) + (vb ? x0b * x0b : 0.f);
        float q1 = (va ? x1a * x1a : 0.f) + (vb ? x1b * x1b : 0.f);
        #pragma unroll
        for (int o = 4; o <= 16; o <<= 1) {
            s0 += __shfl_xor_sync(0xffffffffu, s0, o);
            s1 += __shfl_xor_sync(0xffffffffu, s1, o);
            q0 += __shfl_xor_sync(0xffffffffu, q0, o);
            q1 += __shfl_xor_sync(0xffffffffu, q1, o);
        }
        if (lane < 4) {
            swsum[w * 64 + nt * 8 + lane * 2]     = s0;
            swsum[w * 64 + nt * 8 + lane * 2 + 1] = s1;
            swsq [w * 64 + nt * 8 + lane * 2]     = q0;
            swsq [w * 64 + nt * 8 + lane * 2 + 1] = q1;
        }
    }
    __syncthreads();
    if (t < 64) {
        float s = 0.f, q = 0.f;
        #pragma unroll
        for (int k = 0; k < 8; k++) {
            s += swsum[k * 64 + t];
            q += swsq[k * 64 + t];
        }
        atomicAdd(&g_colsum[t], s);
        atomicAdd(&g_colsq[t], q);
    }
}

// ---------------- K6: BN + ReLU + residual (float4) -------------------------------
__global__ void k_final(const float* __restrict__ h,
                        const float* __restrict__ gamma,
                        const float* __restrict__ beta,
                        float* __restrict__ out) {
    int i = blockIdx.x * blockDim.x + threadIdx.x;
    if (i >= N_NODES * F_DIM / 4) return;
    int j = (i & 15) * 4;
    const float invN = 1.0f / (float)N_NODES;
    float4 cs = *(const float4*)(g_colsum + j);
    float4 cq = *(const float4*)(g_colsq + j);
    float4 gm = *(const float4*)(gamma + j);
    float4 bt = *(const float4*)(beta + j);
    float4 xv = ((const float4*)g_x)[i];
    float4 hv = ((const float4*)h)[i];
    float4 r;
    {
        float mu = cs.x * invN;
        float inv = rsqrtf(cq.x * invN - mu * mu + EPS_BN);
        r.x = hv.x + fmaxf(gm.x * (xv.x - mu) * inv + bt.x, 0.f);
    }
    {
        float mu = cs.y * invN;
        float inv = rsqrtf(cq.y * invN - mu * mu + EPS_BN);
        r.y = hv.y + fmaxf(gm.y * (xv.y - mu) * inv + bt.y, 0.f);
    }
    {
        float mu = cs.z * invN;
        float inv = rsqrtf(cq.z * invN - mu * mu + EPS_BN);
        r.z = hv.z + fmaxf(gm.z * (xv.z - mu) * inv + bt.z, 0.f);
    }
    {
        float mu = cs.w * invN;
        float inv = rsqrtf(cq.w * invN - mu * mu + EPS_BN);
        r.w = hv.w + fmaxf(gm.w * (xv.w - mu) * inv + bt.w, 0.f);
    }
    ((float4*)out)[i] = r;
}

// ---------------- launch ------------------------------------------------------------
extern "C" void kernel_launch(void* const* d_in, const int* in_sizes, int n_in,
                              void* d_out, int out_size) {
    const float* h     = (const float*)d_in[0];
    const int*   src   = (const int*)d_in[1];
    const int*   dst   = (const int*)d_in[2];
    const float* W     = (const float*)d_in[3];
    const float* b     = (const float*)d_in[4];
    const float* gamma = (const float*)d_in[5];
    const float* beta  = (const float*)d_in[6];
    float* out = (float*)d_out;

    cudaFuncSetAttribute(k_gemm_mma, cudaFuncAttributeMaxDynamicSharedMemorySize, SMEM_MM);

    k_hist_wprep<<<(N_EDGES / 4 + 255) / 256, 256>>>(dst, W);
    k_scan<<<NB, 256>>>();
    k_scatter<<<(N_EDGES / 4 + 255) / 256, 256>>>(src, dst);
    k_agg<<<(N_NODES + 7) / 8, 256>>>(h);
    k_gemm_mma<<<(N_NODES + 127) / 128, 256, SMEM_MM>>>(b);
    k_final<<<(N_NODES * F_DIM / 4 + 255) / 256, 256>>>(h, gamma, beta, out);
}

// round 13
// speedup vs baseline: 1.5365x; 1.1295x over previous
#include <cuda_runtime.h>
#include <cuda_fp16.h>
#include <math.h>
#include <stdint.h>

#define N_NODES 50000
#define N_EDGES 800000
#define F_DIM   64
#define AVG_D_LOG 2.833f
#define EPS_STD 1e-5f
#define EPS_BN  1e-5f
#define NB 196   // ceil(50000/256)
#define A_FLAG 0x40000000u
#define P_FLAG 0x80000000u

typedef unsigned long long ull;

// ---------------- device scratch (all zero-initialized at load) ----------------
__device__ int   g_deg[N_NODES];       // zeroed by k_agg after use
__device__ int   g_off[N_NODES];
__device__ int   g_cursor[N_NODES];
__device__ int   g_esrc[N_EDGES];
__device__ unsigned g_pkt[NB];         // scan lookback state; zeroed by k_agg
__device__ unsigned g_a16[(size_t)N_NODES * 128];  // agg rows as fp16x2 words
__device__ float g_c1[N_NODES];
__device__ float g_c2[N_NODES];
__device__ float g_x[(size_t)N_NODES * F_DIM];
__device__ float g_colsum[F_DIM];
__device__ float g_colsq[F_DIM];
__device__ __half g_whi[64 * 768];     // W^T fp16 [n][k]

// ---------------- helpers -------------------------------------------------------
__device__ __forceinline__ uint32_t smem_u32(const void* p) {
    uint32_t r;
    asm("{ .reg .u64 t; cvta.to.shared.u64 t, %1; cvt.u32.u64 %0, t; }"
        : "=r"(r) : "l"(p));
    return r;
}
__device__ __forceinline__ void ldsm4(uint32_t& r0, uint32_t& r1,
                                      uint32_t& r2, uint32_t& r3, uint32_t a) {
    asm volatile("ldmatrix.sync.aligned.m8n8.x4.shared.b16 {%0,%1,%2,%3}, [%4];"
                 : "=r"(r0), "=r"(r1), "=r"(r2), "=r"(r3) : "r"(a));
}
__device__ __forceinline__ void mma_f16(float* d,
                                        uint32_t a0, uint32_t a1, uint32_t a2, uint32_t a3,
                                        uint32_t b0, uint32_t b1) {
    asm volatile(
        "mma.sync.aligned.m16n8k16.row.col.f32.f16.f16.f32 "
        "{%0,%1,%2,%3}, {%4,%5,%6,%7}, {%8,%9}, {%0,%1,%2,%3};"
        : "+f"(d[0]), "+f"(d[1]), "+f"(d[2]), "+f"(d[3])
        : "r"(a0), "r"(a1), "r"(a2), "r"(a3), "r"(b0), "r"(b1));
}
__device__ __forceinline__ uint32_t packh(float x, float y) {
    __half2 t;
    t.x = __float2half_rn(x);
    t.y = __float2half_rn(y);
    return *(uint32_t*)&t;
}
// cp.async 16B with zero-fill (src_bytes = 0 -> zfill, no read)
__device__ __forceinline__ void cp16z(uint32_t s, const void* g, unsigned srcbytes) {
    asm volatile(
        "{ .reg .u64 ga; cvta.to.global.u64 ga, %1;\n\t"
        "cp.async.cg.shared.global [%0], [ga], 16, %2; }"
        :: "r"(s), "l"(g), "r"(srcbytes) : "memory");
}
#define CP_COMMIT() asm volatile("cp.async.commit_group;" ::: "memory")
#define CP_WAIT(n)  asm volatile("cp.async.wait_group %0;" :: "n"(n) : "memory")
// packed f32x2 (add/fma only on this toolchain)
__device__ __forceinline__ void add2(ull& d, ull a) {
    asm("add.rn.f32x2 %0, %0, %1;" : "+l"(d) : "l"(a));
}
__device__ __forceinline__ void fma2(ull& d, ull a) {
    asm("fma.rn.f32x2 %0, %1, %1, %0;" : "+l"(d) : "l"(a));
}
__device__ __forceinline__ float lo32(ull v) { return __uint_as_float((unsigned)v); }
__device__ __forceinline__ float hi32(ull v) { return __uint_as_float((unsigned)(v >> 32)); }

// ---------------- K1: degree histogram (int4) + W fp16 transpose ------------------
__global__ void k_hist_wprep(const int* __restrict__ dst, const float* __restrict__ W) {
    int t = blockIdx.x * blockDim.x + threadIdx.x;
    if (t < N_EDGES / 4) {
        int4 d4 = ((const int4*)dst)[t];
        atomicAdd(&g_deg[d4.x], 1);
        atomicAdd(&g_deg[d4.y], 1);
        atomicAdd(&g_deg[d4.z], 1);
        atomicAdd(&g_deg[d4.w], 1);
    }
    if (t < 768 * 64) {
        int k = t >> 6;
        int n = t & 63;
        g_whi[n * 768 + k] = __float2half_rn(W[t]);
    }
}

// ---------------- K2: single-pass decoupled-lookback scan -------------------------
__global__ void k_scan(void) {
    __shared__ int s[256];
    __shared__ unsigned sprefix;
    int t = threadIdx.x;
    int bidx = blockIdx.x;
    int i = bidx * 256 + t;
    int v = (i < N_NODES) ? g_deg[i] : 0;
    s[t] = v;
    __syncthreads();
    #pragma unroll
    for (int off = 1; off < 256; off <<= 1) {
        int x = (t >= off) ? s[t - off] : 0;
        __syncthreads();
        s[t] += x;
        __syncthreads();
    }
    int total = s[255];

    if (t == 0) {
        unsigned pub = (bidx == 0) ? (P_FLAG | (unsigned)total)
                                   : (A_FLAG | (unsigned)total);
        atomicExch(&g_pkt[bidx], pub);
        if (bidx == 0) sprefix = 0;
    }

    if (bidx > 0 && t < 32) {
        unsigned running = 0;
        int idx = bidx - 1;
        for (;;) {
            int j = idx - t;
            unsigned p;
            if (j >= 0) {
                do { p = ((volatile unsigned*)g_pkt)[j]; } while (p == 0);
            } else {
                p = P_FLAG;
            }
            unsigned pm = __ballot_sync(0xffffffffu, (p & P_FLAG) != 0);
            unsigned val = p & 0x3fffffffu;
            if (pm) {
                int k = __ffs(pm) - 1;
                unsigned contrib = (t <= k) ? val : 0;
                #pragma unroll
                for (int o = 16; o > 0; o >>= 1)
                    contrib += __shfl_down_sync(0xffffffffu, contrib, o);
                if (t == 0) sprefix = running + contrib;
                break;
            } else {
                unsigned contrib = (j >= 0) ? val : 0;
                #pragma unroll
                for (int o = 16; o > 0; o >>= 1)
                    contrib += __shfl_down_sync(0xffffffffu, contrib, o);
                running += __shfl_sync(0xffffffffu, contrib, 0);
                idx -= 32;
            }
        }
        if (t == 0)
            atomicExch(&g_pkt[bidx], P_FLAG | (sprefix + (unsigned)total));
    }
    __syncthreads();

    if (i < N_NODES) {
        int ex = (int)sprefix + s[t] - v;
        g_off[i] = ex;
        g_cursor[i] = ex;
    }
}

// ---------------- K3: scatter edges, 4 per thread (MLP=4) -------------------------
__global__ void k_scatter(const int* __restrict__ src, const int* __restrict__ dst) {
    int t = blockIdx.x * blockDim.x + threadIdx.x;
    if (t >= N_EDGES / 4) return;
    int4 d4 = ((const int4*)dst)[t];
    int4 s4 = ((const int4*)src)[t];
    int p0 = atomicAdd(&g_cursor[d4.x], 1);
    int p1 = atomicAdd(&g_cursor[d4.y], 1);
    int p2 = atomicAdd(&g_cursor[d4.z], 1);
    int p3 = atomicAdd(&g_cursor[d4.w], 1);
    g_esrc[p0] = s4.x;
    g_esrc[p1] = s4.y;
    g_esrc[p2] = s4.z;
    g_esrc[p3] = s4.w;
}

// ---------------- K4: warp-per-node aggregation (single banks, regs=32) -----------
__global__ void k_agg(const float* __restrict__ h) {
    if (blockIdx.x == 0) {
        int tt = threadIdx.x;
        if (tt < F_DIM) { g_colsum[tt] = 0.f; g_colsq[tt] = 0.f; }
        if (tt < NB) g_pkt[tt] = 0u;
    }

    int warp = (blockIdx.x * blockDim.x + threadIdx.x) >> 5;
    int lane = threadIdx.x & 31;
    if (warp >= N_NODES) return;

    int start = g_off[warp];
    int d = g_deg[warp];
    int end = start + d;

    const ull* hl = (const ull*)h + lane;

    ull sum = 0ull;
    ull sq  = 0ull;
    float mx0 = -3.402823466e38f, mx1 = -3.402823466e38f;
    float mn0 =  3.402823466e38f, mn1 =  3.402823466e38f;

    int e = start;
    while (e < end && (e & 3)) {
        ull va = hl[g_esrc[e] * 32];
        add2(sum, va); fma2(sq, va);
        mx0 = fmaxf(mx0, lo32(va)); mx1 = fmaxf(mx1, hi32(va));
        mn0 = fminf(mn0, lo32(va)); mn1 = fminf(mn1, hi32(va));
        e++;
    }
    for (; e + 4 <= end; e += 4) {
        int4 s4 = *(const int4*)(g_esrc + e);
        ull va = hl[s4.x * 32];
        ull vb = hl[s4.y * 32];
        ull vc = hl[s4.z * 32];
        ull vd = hl[s4.w * 32];
        add2(sum, va); fma2(sq, va);
        mx0 = fmaxf(mx0, lo32(va)); mx1 = fmaxf(mx1, hi32(va));
        mn0 = fminf(mn0, lo32(va)); mn1 = fminf(mn1, hi32(va));
        add2(sum, vb); fma2(sq, vb);
        mx0 = fmaxf(mx0, lo32(vb)); mx1 = fmaxf(mx1, hi32(vb));
        mn0 = fminf(mn0, lo32(vb)); mn1 = fminf(mn1, hi32(vb));
        add2(sum, vc); fma2(sq, vc);
        mx0 = fmaxf(mx0, lo32(vc)); mx1 = fmaxf(mx1, hi32(vc));
        mn0 = fminf(mn0, lo32(vc)); mn1 = fminf(mn1, hi32(vc));
        add2(sum, vd); fma2(sq, vd);
        mx0 = fmaxf(mx0, lo32(vd)); mx1 = fmaxf(mx1, hi32(vd));
        mn0 = fminf(mn0, lo32(vd)); mn1 = fminf(mn1, hi32(vd));
    }
    for (; e < end; e++) {
        ull va = hl[g_esrc[e] * 32];
        add2(sum, va); fma2(sq, va);
        mx0 = fmaxf(mx0, lo32(va)); mx1 = fmaxf(mx1, hi32(va));
        mn0 = fminf(mn0, lo32(va)); mn1 = fminf(mn1, hi32(va));
    }

    unsigned* ar = g_a16 + (size_t)warp * 128 + lane;
    if (d > 0) {
        float inv = 1.0f / (float)d;
        float s0 = lo32(sum), s1 = hi32(sum);
        float q0 = lo32(sq),  q1 = hi32(sq);
        float mean0 = s0 * inv, mean1 = s1 * inv;
        float var0 = fmaxf(q0 * inv - mean0 * mean0, 0.f);
        float var1 = fmaxf(q1 * inv - mean1 * mean1, 0.f);
        float std0 = sqrtf(var0 + EPS_STD);
        float std1 = sqrtf(var1 + EPS_STD);
        // sections: 0=mean 1=max 2=min 3=std; 32 fp16x2 words each
        ar[0]  = packh(mean0, mean1);
        ar[32] = packh(mx0, mx1);
        ar[64] = packh(mn0, mn1);
        ar[96] = packh(std0, std1);
        if (lane == 0) {
            float logD = logf((float)d + 1.0f);
            g_c1[warp] = logD / AVG_D_LOG;
            g_c2[warp] = AVG_D_LOG / fmaxf(logD, 1e-12f);
        }
    } else {
        ar[0] = 0u; ar[32] = 0u; ar[64] = 0u; ar[96] = 0u;
        if (lane == 0) { g_c1[warp] = 0.f; g_c2[warp] = 0.f; }
    }
    if (lane == 0) g_deg[warp] = 0;
}

// ---------------- K5: mma.sync fp16 GEMM, double-buffered cp.async pipeline --------
#define AST 144
#define SBUF  (64 * AST)              // 9216
#define SB_OFF (128 * AST)            // 18432 (A region size)
#define BUFSZ (SB_OFF + 3 * SBUF)     // 46080 per buffer
#define SMEM_MM (2 * BUFSZ)           // 92160

__global__ void __launch_bounds__(256)
k_gemm_mma(const float* __restrict__ bias) {
    extern __shared__ char smem[];
    const uint32_t sb = smem_u32(smem);
    int t = threadIdx.x;
    int w = t >> 5;
    int lane = t & 31;
    int m0 = blockIdx.x * 128;

    float acc[3][8][4];
    #pragma unroll
    for (int p = 0; p < 3; p++)
        #pragma unroll
        for (int nt = 0; nt < 8; nt++)
            #pragma unroll
            for (int j = 0; j < 4; j++) acc[p][nt][j] = 0.f;

    // precomputed per-thread load geometry
    const int arow = t >> 3;          // A: rows arow, arow+32, arow+64, arow+96
    const int ag   = t & 7;
    const int bp   = t >> 9;          // always 0 for t<512; pattern below uses idx
    (void)bp;

    // issue cp.async loads for chunk c into buffer at base `buf`
    auto load_chunk = [&](int c, uint32_t buf) {
        #pragma unroll
        for (int it = 0; it < 4; it++) {
            int row = arow + it * 32;
            int gm = m0 + row;
            unsigned ok = (gm < N_NODES) ? 16u : 0u;
            int gmc = (gm < N_NODES) ? gm : 0;
            cp16z(buf + row * AST + ag * 16,
                  g_a16 + (size_t)gmc * 128 + c * 32 + ag * 4, ok);
        }
        #pragma unroll
        for (int it = 0; it < 6; it++) {
            int idx = t + it * 256;     // 0..1535
            int p = idx >> 9;
            int rem = idx & 511;
            int row = rem >> 3;
            int g = rem & 7;
            cp16z(buf + SB_OFF + p * SBUF + row * AST + g * 16,
                  g_whi + row * 768 + p * 256 + c * 64 + g * 8, 16u);
        }
        CP_COMMIT();
    };

    load_chunk(0, sb);

    for (int c = 0; c < 4; c++) {
        if (c < 3) {
            load_chunk(c + 1, sb + ((c + 1) & 1) * BUFSZ);
            CP_WAIT(1);
        } else {
            CP_WAIT(0);
        }
        __syncthreads();

        uint32_t buf = sb + (c & 1) * BUFSZ;

        #pragma unroll
        for (int ks = 0; ks < 4; ks++) {
            int ar = w * 16 + (lane & 15);
            uint32_t aoff = (uint32_t)(ar * AST + ks * 32 + ((lane >> 4) << 4));
            uint32_t a0, a1, a2, a3;
            ldsm4(a0, a1, a2, a3, buf + aoff);

            #pragma unroll
            for (int np = 0; np < 4; np++) {
                int nrow = np * 16 + (lane & 7) + ((lane & 16) ? 8 : 0);
                uint32_t boff = (uint32_t)(nrow * AST + ks * 32 + ((lane & 8) ? 16 : 0));
                #pragma unroll
                for (int p = 0; p < 3; p++) {
                    uint32_t b0, b1, b2, b3;
                    ldsm4(b0, b1, b2, b3, buf + SB_OFF + p * SBUF + boff);
                    mma_f16(acc[p][np * 2],     a0, a1, a2, a3, b0, b1);
                    mma_f16(acc[p][np * 2 + 1], a0, a1, a2, a3, b2, b3);
                }
            }
        }
        __syncthreads();   // protect buffer reuse by next prefetch
    }

    // ---- epilogue: x = D0 + c1*D1 + c2*D2 + bias; fused BN column stats ----
    float* swsum = (float*)smem;
    float* swsq  = (float*)(smem + 2048);

    int rowA = m0 + w * 16 + (lane >> 2);
    int rowB = rowA + 8;
    bool va = rowA < N_NODES, vb = rowB < N_NODES;
    float c1a = 0.f, c2a = 0.f, c1b = 0.f, c2b = 0.f;
    if (va) { c1a = g_c1[rowA]; c2a = g_c2[rowA]; }
    if (vb) { c1b = g_c1[rowB]; c2b = g_c2[rowB]; }

    #pragma unroll
    for (int nt = 0; nt < 8; nt++) {
        int col = nt * 8 + (lane & 3) * 2;
        float b0 = bias[col];
        float b1 = bias[col + 1];
        float x0a = acc[0][nt][0] + c1a * acc[1][nt][0] + c2a * acc[2][nt][0] + b0;
        float x1a = acc[0][nt][1] + c1a * acc[1][nt][1] + c2a * acc[2][nt][1] + b1;
        float x0b = acc[0][nt][2] + c1b * acc[1][nt][2] + c2b * acc[2][nt][2] + b0;
        float x1b = acc[0][nt][3] + c1b * acc[1][nt][3] + c2b * acc[2][nt][3] + b1;
        if (va) *(float2*)(g_x + (size_t)rowA * 64 + col) = make_float2(x0a, x1a);
        if (vb) *(float2*)(g_x + (size_t)rowB * 64 + col) = make_float2(x0b, x1b);

        float s0 = (va ? x0a : 0.f) + (vb ? x0b : 0.f);
        float s1 = (va ? x1a : 0.f) + (vb ? x1b : 0.f);
        float q0 = (va ? x0a * x0a : 0.f) + (vb ? x0b * x0b : 0.f);
        float q1 = (va ? x1a * x1a : 0.f) + (vb ? x1b * x1b : 0.f);
        #pragma unroll
        for (int o = 4; o <= 16; o <<= 1) {
            s0 += __shfl_xor_sync(0xffffffffu, s0, o);
            s1 += __shfl_xor_sync(0xffffffffu, s1, o);
            q0 += __shfl_xor_sync(0xffffffffu, q0, o);
            q1 += __shfl_xor_sync(0xffffffffu, q1, o);
        }
        if (lane < 4) {
            swsum[w * 64 + nt * 8 + lane * 2]     = s0;
            swsum[w * 64 + nt * 8 + lane * 2 + 1] = s1;
            swsq [w * 64 + nt * 8 + lane * 2]     = q0;
            swsq [w * 64 + nt * 8 + lane * 2 + 1] = q1;
        }
    }
    __syncthreads();
    if (t < 64) {
        float s = 0.f, q = 0.f;
        #pragma unroll
        for (int k = 0; k < 8; k++) {
            s += swsum[k * 64 + t];
            q += swsq[k * 64 + t];
        }
        atomicAdd(&g_colsum[t], s);
        atomicAdd(&g_colsq[t], q);
    }
}

// ---------------- K6: BN + ReLU + residual (float4) -------------------------------
__global__ void k_final(const float* __restrict__ h,
                        const float* __restrict__ gamma,
                        const float* __restrict__ beta,
                        float* __restrict__ out) {
    int i = blockIdx.x * blockDim.x + threadIdx.x;
    if (i >= N_NODES * F_DIM / 4) return;
    int j = (i & 15) * 4;
    const float invN = 1.0f / (float)N_NODES;
    float4 cs = *(const float4*)(g_colsum + j);
    float4 cq = *(const float4*)(g_colsq + j);
    float4 gm = *(const float4*)(gamma + j);
    float4 bt = *(const float4*)(beta + j);
    float4 xv = ((const float4*)g_x)[i];
    float4 hv = ((const float4*)h)[i];
    float4 r;
    {
        float mu = cs.x * invN;
        float inv = rsqrtf(cq.x * invN - mu * mu + EPS_BN);
        r.x = hv.x + fmaxf(gm.x * (xv.x - mu) * inv + bt.x, 0.f);
    }
    {
        float mu = cs.y * invN;
        float inv = rsqrtf(cq.y * invN - mu * mu + EPS_BN);
        r.y = hv.y + fmaxf(gm.y * (xv.y - mu) * inv + bt.y, 0.f);
    }
    {
        float mu = cs.z * invN;
        float inv = rsqrtf(cq.z * invN - mu * mu + EPS_BN);
        r.z = hv.z + fmaxf(gm.z * (xv.z - mu) * inv + bt.z, 0.f);
    }
    {
        float mu = cs.w * invN;
        float inv = rsqrtf(cq.w * invN - mu * mu + EPS_BN);
        r.w = hv.w + fmaxf(gm.w * (xv.w - mu) * inv + bt.w, 0.f);
    }
    ((float4*)out)[i] = r;
}

// ---------------- launch ------------------------------------------------------------
extern "C" void kernel_launch(void* const* d_in, const int* in_sizes, int n_in,
                              void* d_out, int out_size) {
    const float* h     = (const float*)d_in[0];
    const int*   src   = (const int*)d_in[1];
    const int*   dst   = (const int*)d_in[2];
    const float* W     = (const float*)d_in[3];
    const float* b     = (const float*)d_in[4];
    const float* gamma = (const float*)d_in[5];
    const float* beta  = (const float*)d_in[6];
    float* out = (float*)d_out;

    cudaFuncSetAttribute(k_gemm_mma, cudaFuncAttributeMaxDynamicSharedMemorySize, SMEM_MM);

    k_hist_wprep<<<(N_EDGES / 4 + 255) / 256, 256>>>(dst, W);
    k_scan<<<NB, 256>>>();
    k_scatter<<<(N_EDGES / 4 + 255) / 256, 256>>>(src, dst);
    k_agg<<<(N_NODES + 7) / 8, 256>>>(h);
    k_gemm_mma<<<(N_NODES + 127) / 128, 256, SMEM_MM>>>(b);
    k_final<<<(N_NODES * F_DIM / 4 + 255) / 256, 256>>>(h, gamma, beta, out);
}